// round 12
// baseline (speedup 1.0000x reference)
#include <cuda_runtime.h>
#include <cuda_fp16.h>
#include <math.h>

#define N_NODES 50000
#define N_EDGES 800000
#define IN_F    128
#define HC      256
#define G_GRAPHS 64
#define OUT_F   64
#define NLAYERS 4

// ---------------- scratch (static device allocations; no cudaMalloc) ----------------
__device__ float  g_qs[(size_t)N_NODES * 512];    // [q|s] per node, fp32
__device__ __half g_kv[(size_t)N_NODES * 512];    // [k|v] per node, fp16
__device__ __half g_hh[(size_t)N_NODES * HC];     // layer activations, fp16
__device__ __half g_xh[(size_t)N_NODES * IN_F];   // input x converted to fp16
__device__ __half g_Wc[1024 * 256];               // packed W^T [1024 cols][K], fp16
__device__ float  g_bc[1024];
__device__ int    g_cnt[N_NODES];
__device__ int    g_cur[N_NODES];
__device__ int    g_off[N_NODES + 1];
__device__ int    g_psrc[N_EDGES];
__device__ float  g_pool[G_GRAPHS * HC];
__device__ int    g_gcnt[G_GRAPHS];

// ---------------- CSR build ----------------
__global__ void zero_csr_kernel() {
    int i = blockIdx.x * blockDim.x + threadIdx.x;
    if (i < N_NODES) { g_cnt[i] = 0; g_cur[i] = 0; }
}

__global__ void hist_kernel(const int* __restrict__ dst) {
    int e = blockIdx.x * blockDim.x + threadIdx.x;
    if (e < N_EDGES) atomicAdd(&g_cnt[dst[e]], 1);
}

__global__ void scan_kernel() {
    __shared__ int buf[1024];
    __shared__ int carry;
    int tid = threadIdx.x;
    if (tid == 0) carry = 0;
    __syncthreads();
    for (int base = 0; base < N_NODES; base += 1024) {
        int i = base + tid;
        int v = (i < N_NODES) ? g_cnt[i] : 0;
        buf[tid] = v;
        __syncthreads();
        #pragma unroll
        for (int ofs = 1; ofs < 1024; ofs <<= 1) {
            int t = (tid >= ofs) ? buf[tid - ofs] : 0;
            __syncthreads();
            buf[tid] += t;
            __syncthreads();
        }
        int excl = buf[tid] - v + carry;
        if (i < N_NODES) g_off[i] = excl;
        __syncthreads();
        if (tid == 1023) carry += buf[1023];
        __syncthreads();
    }
    if (tid == 0) g_off[N_NODES] = carry;
}

__global__ void scatter_kernel(const int* __restrict__ src, const int* __restrict__ dst) {
    int e = blockIdx.x * blockDim.x + threadIdx.x;
    if (e < N_EDGES) {
        int d = dst[e];
        int p = atomicAdd(&g_cur[d], 1);
        g_psrc[g_off[d] + p] = src[e];
    }
}

// ---------------- x -> fp16 conversion (once) ----------------
__global__ void xcvt_kernel(const float* __restrict__ x) {
    int i = blockIdx.x * blockDim.x + threadIdx.x;
    int total = N_NODES * IN_F / 2;
    if (i < total) {
        float2 v = *(const float2*)(x + (size_t)i * 2);
        *(__half2*)(g_xh + (size_t)i * 2) = __floats2half2_rn(v.x, v.y);
    }
}

// ---------------- weight packing: [F,256]x4 -> W^T [1024][F], fp16 ----------------
__global__ void pack_kernel(const float* __restrict__ Wq, const float* __restrict__ Wk,
                            const float* __restrict__ Wv, const float* __restrict__ Ws,
                            const float* __restrict__ bq, const float* __restrict__ bk,
                            const float* __restrict__ bv, const float* __restrict__ bs,
                            int F) {
    int idx = blockIdx.x * blockDim.x + threadIdx.x;
    int total = F * 1024;
    if (idx < total) {
        int f   = idx & (F - 1);
        int col = idx / F;
        int sel = col >> 8;
        int c   = col & 255;
        const float* W = (sel == 0) ? Wq : (sel == 1) ? Wk : (sel == 2) ? Wv : Ws;
        g_Wc[idx] = __float2half_rn(W[f * 256 + c]);
    }
    if (idx < 1024) {
        int sel = idx >> 8, c = idx & 255;
        const float* b = (sel == 0) ? bq : (sel == 1) ? bk : (sel == 2) ? bv : bs;
        g_bc[idx] = b[c];
    }
}

// ---------------- fp16 tensor-core GEMM (m16n8k16), 128x256 tile, 64x64 warp tiles ----------------
#define GBM 128
#define GBN 256
#define GBK 32
#define HPITCH 40     // 40 halfs = 80B pitch; conflict-free for ldmatrix 8-row access
#define ABUF (GBM * HPITCH)           // 5120 halfs per A buffer
#define BBUF (GBN * HPITCH)           // 10240 halfs per B buffer
#define SMEM_HALFS (2 * ABUF + 2 * BBUF)   // 30720 halfs = 61440 bytes

__device__ __forceinline__ void cp_async16(void* smem_dst, const void* gsrc, int src_bytes) {
    unsigned sdst = (unsigned)__cvta_generic_to_shared(smem_dst);
    asm volatile("cp.async.ca.shared.global [%0], [%1], 16, %2;"
                 :: "r"(sdst), "l"(gsrc), "r"(src_bytes));
}
__device__ __forceinline__ void cp_async_commit() {
    asm volatile("cp.async.commit_group;");
}
template <int NN>
__device__ __forceinline__ void cp_async_wait() {
    asm volatile("cp.async.wait_group %0;" :: "n"(NN));
}

__device__ __forceinline__ void ldsm_x4(unsigned& r0, unsigned& r1, unsigned& r2, unsigned& r3,
                                        unsigned addr) {
    asm volatile("ldmatrix.sync.aligned.m8n8.x4.shared.b16 {%0,%1,%2,%3}, [%4];"
                 : "=r"(r0), "=r"(r1), "=r"(r2), "=r"(r3) : "r"(addr));
}

__device__ __forceinline__ void store_seg(int row, int col, float vx, float vy) {
    if (col < 256) {
        *(float2*)(g_qs + (size_t)row * 512 + col) = make_float2(vx, vy);
    } else if (col < 768) {
        *(__half2*)(g_kv + (size_t)row * 512 + (col - 256)) = __floats2half2_rn(vx, vy);
    } else {
        *(float2*)(g_qs + (size_t)row * 512 + 256 + (col - 768)) = make_float2(vx, vy);
    }
}

__global__ __launch_bounds__(256) void gemm_tc_kernel(const __half* __restrict__ A, int M, int K) {
    extern __shared__ __half sm[];
    __half* AsBuf[2] = { sm, sm + ABUF };
    __half* BsBuf[2] = { sm + 2 * ABUF, sm + 2 * ABUF + BBUF };

    int tid  = threadIdx.x;
    int lane = tid & 31;
    int wid  = tid >> 5;
    int gid  = lane >> 2;
    int tig  = lane & 3;
    int warpM = wid & 1;    // 2 along M, 64 rows each
    int warpN = wid >> 1;   // 4 along N, 64 cols each

    int mBase = blockIdx.y * GBM;
    int nBase = blockIdx.x * GBN;

    // ldmatrix per-thread offsets
    int aRowOff = lane & 15;
    int aKOff   = (lane >> 4) << 3;               // 0 or 8
    int bColOff = ((lane >> 4) << 3) + (lane & 7); // matrices 0,1 -> cols+0..7; 2,3 -> +8..15
    int bKOff   = ((lane >> 3) & 1) << 3;          // matrices 0,2 -> k+0; 1,3 -> k+8

    float c[4][8][4];
    #pragma unroll
    for (int i = 0; i < 4; i++)
        #pragma unroll
        for (int j = 0; j < 8; j++)
            #pragma unroll
            for (int r = 0; r < 4; r++) c[i][j][r] = 0.f;

    int nTiles = K / GBK;

    // cp.async tile loader: A = 512 chunks (128 rows x 4), B = 1024 chunks (256 cols x 4)
    auto load_tile = [&](int bufIdx, int k0) {
        __half* As = AsBuf[bufIdx];
        __half* Bs = BsBuf[bufIdx];
        #pragma unroll
        for (int t = 0; t < 2; t++) {
            int idx = tid + t * 256;            // 0..511
            int row = idx >> 2;
            int ck  = idx & 3;
            int gm  = mBase + row;
            int ok  = (gm < M) ? 16 : 0;
            const __half* src = A + (size_t)((gm < M) ? gm : 0) * K + k0 + ck * 8;
            cp_async16(&As[row * HPITCH + ck * 8], src, ok);
        }
        #pragma unroll
        for (int t = 0; t < 4; t++) {
            int idx = tid + t * 256;            // 0..1023
            int col = idx >> 2;
            int ck  = idx & 3;
            const __half* src = g_Wc + (size_t)(nBase + col) * K + k0 + ck * 8;
            cp_async16(&Bs[col * HPITCH + ck * 8], src, 16);
        }
        cp_async_commit();
    };

    load_tile(0, 0);

    for (int kt = 0; kt < nTiles; kt++) {
        int buf = kt & 1;
        if (kt + 1 < nTiles) {
            load_tile(buf ^ 1, (kt + 1) * GBK);
            cp_async_wait<1>();
        } else {
            cp_async_wait<0>();
        }
        __syncthreads();

        unsigned asb = (unsigned)__cvta_generic_to_shared(AsBuf[buf]);
        unsigned bsb = (unsigned)__cvta_generic_to_shared(BsBuf[buf]);
        #pragma unroll
        for (int ks = 0; ks < 2; ks++) {
            int kk = ks * 16;
            unsigned af[4][4];
            #pragma unroll
            for (int mt = 0; mt < 4; mt++) {
                unsigned addr = asb +
                    ((warpM * 64 + mt * 16 + aRowOff) * HPITCH + kk + aKOff) * 2;
                ldsm_x4(af[mt][0], af[mt][1], af[mt][2], af[mt][3], addr);
            }
            unsigned bf[8][2];
            #pragma unroll
            for (int j = 0; j < 4; j++) {       // pairs of n-tiles
                unsigned addr = bsb +
                    ((warpN * 64 + j * 16 + bColOff) * HPITCH + kk + bKOff) * 2;
                ldsm_x4(bf[2 * j][0], bf[2 * j][1], bf[2 * j + 1][0], bf[2 * j + 1][1], addr);
            }
            #pragma unroll
            for (int mt = 0; mt < 4; mt++)
                #pragma unroll
                for (int nt = 0; nt < 8; nt++) {
                    asm volatile(
                        "mma.sync.aligned.m16n8k16.row.col.f32.f16.f16.f32 "
                        "{%0,%1,%2,%3}, {%4,%5,%6,%7}, {%8,%9}, {%0,%1,%2,%3};"
                        : "+f"(c[mt][nt][0]), "+f"(c[mt][nt][1]),
                          "+f"(c[mt][nt][2]), "+f"(c[mt][nt][3])
                        : "r"(af[mt][0]), "r"(af[mt][1]), "r"(af[mt][2]), "r"(af[mt][3]),
                          "r"(bf[nt][0]), "r"(bf[nt][1]));
                }
        }
        __syncthreads();
    }

    // epilogue: bias + routed store
    #pragma unroll
    for (int nt = 0; nt < 8; nt++) {
        int col = nBase + warpN * 64 + nt * 8 + tig * 2;
        float2 bias = *(const float2*)(g_bc + col);
        #pragma unroll
        for (int mt = 0; mt < 4; mt++) {
            int row0 = mBase + warpM * 64 + mt * 16 + gid;
            if (row0 < M)
                store_seg(row0, col, c[mt][nt][0] + bias.x, c[mt][nt][1] + bias.y);
            int row1 = row0 + 8;
            if (row1 < M)
                store_seg(row1, col, c[mt][nt][2] + bias.x, c[mt][nt][3] + bias.y);
        }
    }
}

// ---------------- attention: one warp per dst node, depth-2 index prefetch ----------------
__global__ __launch_bounds__(256) void attn_kernel() {
    int warp = (blockIdx.x * blockDim.x + threadIdx.x) >> 5;
    int lane = threadIdx.x & 31;
    if (warp >= N_NODES) return;

    const float* base_q = g_qs + (size_t)warp * 512 + lane * 8;
    float4 q0 = *(const float4*)(base_q);
    float4 q1 = *(const float4*)(base_q + 4);

    float m = -INFINITY, s = 0.f;
    float4 a0 = make_float4(0.f, 0.f, 0.f, 0.f);
    float4 a1 = make_float4(0.f, 0.f, 0.f, 0.f);

    int e0 = g_off[warp], e1 = g_off[warp + 1];

    uint4 kc = make_uint4(0, 0, 0, 0), vc = make_uint4(0, 0, 0, 0);
    int sB = 0;
    if (e0 < e1) {
        const __half* kvb = g_kv + (size_t)g_psrc[e0] * 512 + lane * 8;
        kc = *(const uint4*)(kvb);
        vc = *(const uint4*)(kvb + 256);
        if (e0 + 1 < e1) sB = g_psrc[e0 + 1];
    }

    for (int i = e0; i < e1; i++) {
        uint4 kcur = kc, vcur = vc;
        int sC = (i + 2 < e1) ? g_psrc[i + 2] : 0;
        if (i + 1 < e1) {
            const __half* kvb = g_kv + (size_t)sB * 512 + lane * 8;
            kc = *(const uint4*)(kvb);
            vc = *(const uint4*)(kvb + 256);
        }
        sB = sC;

        float2 k01 = __half22float2(*(const __half2*)&kcur.x);
        float2 k23 = __half22float2(*(const __half2*)&kcur.y);
        float2 k45 = __half22float2(*(const __half2*)&kcur.z);
        float2 k67 = __half22float2(*(const __half2*)&kcur.w);

        float d = q0.x * k01.x + q0.y * k01.y + q0.z * k23.x + q0.w * k23.y
                + q1.x * k45.x + q1.y * k45.y + q1.z * k67.x + q1.w * k67.y;
        d += __shfl_xor_sync(0xFFFFFFFFu, d, 1);
        d += __shfl_xor_sync(0xFFFFFFFFu, d, 2);
        float logit = d * 0.17677669529663687f;   // 1/sqrt(32)

        float mN = fmaxf(m, logit);
        float sc = __expf(m - mN);
        float p  = __expf(logit - mN);
        m = mN;
        s = s * sc + p;

        float2 v01 = __half22float2(*(const __half2*)&vcur.x);
        float2 v23 = __half22float2(*(const __half2*)&vcur.y);
        float2 v45 = __half22float2(*(const __half2*)&vcur.z);
        float2 v67 = __half22float2(*(const __half2*)&vcur.w);

        a0.x = a0.x * sc + p * v01.x; a0.y = a0.y * sc + p * v01.y;
        a0.z = a0.z * sc + p * v23.x; a0.w = a0.w * sc + p * v23.y;
        a1.x = a1.x * sc + p * v45.x; a1.y = a1.y * sc + p * v45.y;
        a1.z = a1.z * sc + p * v67.x; a1.w = a1.w * sc + p * v67.y;
    }

    float inv = 1.f / (s + 1e-16f);
    const float* sb = g_qs + (size_t)warp * 512 + 256 + lane * 8;
    float4 s0 = *(const float4*)(sb);
    float4 s1 = *(const float4*)(sb + 4);
    float r0 = fmaxf(a0.x * inv + s0.x, 0.f);
    float r1 = fmaxf(a0.y * inv + s0.y, 0.f);
    float r2 = fmaxf(a0.z * inv + s0.z, 0.f);
    float r3 = fmaxf(a0.w * inv + s0.w, 0.f);
    float r4 = fmaxf(a1.x * inv + s1.x, 0.f);
    float r5 = fmaxf(a1.y * inv + s1.y, 0.f);
    float r6 = fmaxf(a1.z * inv + s1.z, 0.f);
    float r7 = fmaxf(a1.w * inv + s1.w, 0.f);

    __half* hb = g_hh + (size_t)warp * 256 + lane * 8;
    uint4 packed;
    *(__half2*)&packed.x = __floats2half2_rn(r0, r1);
    *(__half2*)&packed.y = __floats2half2_rn(r2, r3);
    *(__half2*)&packed.z = __floats2half2_rn(r4, r5);
    *(__half2*)&packed.w = __floats2half2_rn(r6, r7);
    *(uint4*)hb = packed;
}

// ---------------- pooling ----------------
__global__ void zero_pool_kernel() {
    int i = blockIdx.x * blockDim.x + threadIdx.x;
    if (i < G_GRAPHS * HC) g_pool[i] = 0.f;
    if (i < G_GRAPHS) g_gcnt[i] = 0;
}

__global__ __launch_bounds__(256) void pool_kernel(const int* __restrict__ batch) {
    int c = threadIdx.x;
    int per = (N_NODES + gridDim.x - 1) / gridDim.x;
    int start = blockIdx.x * per;
    int end = min(N_NODES, start + per);
    if (start >= end) return;
    int cur = batch[start];
    float acc = 0.f;
    int cnt = 0;
    for (int i = start; i < end; i++) {
        int b = batch[i];
        if (b != cur) {
            atomicAdd(&g_pool[cur * HC + c], acc);
            if (c == 0) atomicAdd(&g_gcnt[cur], cnt);
            acc = 0.f; cnt = 0; cur = b;
        }
        acc += __half2float(g_hh[(size_t)i * HC + c]);
        cnt++;
    }
    atomicAdd(&g_pool[cur * HC + c], acc);
    if (c == 0) atomicAdd(&g_gcnt[cur], cnt);
}

__global__ void fc_kernel(const float* __restrict__ Wfc, const float* __restrict__ bfc,
                          float* __restrict__ out) {
    int g = blockIdx.x;
    int o = threadIdx.x;
    __shared__ float p[HC];
    float inv = 1.f / fmaxf((float)g_gcnt[g], 1.f);
    for (int i = o; i < HC; i += OUT_F) p[i] = g_pool[g * HC + i] * inv;
    __syncthreads();
    float acc = bfc[o];
    #pragma unroll 8
    for (int f = 0; f < HC; f++) acc += p[f] * Wfc[f * OUT_F + o];
    out[g * OUT_F + o] = acc;
}

// ---------------- launch ----------------
extern "C" void kernel_launch(void* const* d_in, const int* in_sizes, int n_in,
                              void* d_out, int out_size) {
    const float* x    = (const float*)d_in[0];
    const int*   ei   = (const int*)d_in[1];
    const int*   src  = ei;
    const int*   dst  = ei + N_EDGES;
    const int*   batch = (const int*)d_in[2];
    const float* Wq0 = (const float*)d_in[3];
    const float* bq0 = (const float*)d_in[4];
    const float* Wk0 = (const float*)d_in[5];
    const float* bk0 = (const float*)d_in[6];
    const float* Wv0 = (const float*)d_in[7];
    const float* bv0 = (const float*)d_in[8];
    const float* Ws0 = (const float*)d_in[9];
    const float* bs0 = (const float*)d_in[10];
    const float* Wq  = (const float*)d_in[11];
    const float* bq  = (const float*)d_in[12];
    const float* Wk  = (const float*)d_in[13];
    const float* bk  = (const float*)d_in[14];
    const float* Wv  = (const float*)d_in[15];
    const float* bv  = (const float*)d_in[16];
    const float* Ws  = (const float*)d_in[17];
    const float* bs  = (const float*)d_in[18];
    const float* Wfc = (const float*)d_in[19];
    const float* bfc = (const float*)d_in[20];
    float* out = (float*)d_out;

    const int TB = 256;
    const int smemBytes = SMEM_HALFS * 2;    // 61440
    dim3 ggrid(1024 / GBN, (N_NODES + GBM - 1) / GBM);   // (4, 391)
    int attnBlocks = (N_NODES + 7) / 8;

    __half* xh = nullptr;
    __half* hh = nullptr;
    cudaGetSymbolAddress((void**)&xh, g_xh);
    cudaGetSymbolAddress((void**)&hh, g_hh);

    cudaFuncSetAttribute(gemm_tc_kernel, cudaFuncAttributeMaxDynamicSharedMemorySize, smemBytes);

    // gemm_tc_kernel is the 4th launch (ncu capture slot).
    xcvt_kernel<<<(N_NODES * IN_F / 2 + TB - 1) / TB, TB>>>(x);                              // 1
    pack_kernel<<<(IN_F * 1024 + TB - 1) / TB, TB>>>(Wq0, Wk0, Wv0, Ws0,
                                                     bq0, bk0, bv0, bs0, IN_F);              // 2
    zero_csr_kernel<<<(N_NODES + TB - 1) / TB, TB>>>();                                      // 3
    gemm_tc_kernel<<<ggrid, 256, smemBytes>>>(xh, N_NODES, IN_F);                            // 4 (profiled)
    hist_kernel<<<(N_EDGES + TB - 1) / TB, TB>>>(dst);                                       // 5
    scan_kernel<<<1, 1024>>>();                                                              // 6
    scatter_kernel<<<(N_EDGES + TB - 1) / TB, TB>>>(src, dst);                               // 7
    attn_kernel<<<attnBlocks, 256>>>();                                                      // 8

    // layers 1..3 (HC -> HC)
    for (int l = 0; l < NLAYERS - 1; l++) {
        const float* wq = Wq + (size_t)l * HC * HC;
        const float* wk = Wk + (size_t)l * HC * HC;
        const float* wv = Wv + (size_t)l * HC * HC;
        const float* ws = Ws + (size_t)l * HC * HC;
        pack_kernel<<<(HC * 1024 + TB - 1) / TB, TB>>>(wq, wk, wv, ws,
                                                       bq + l * HC, bk + l * HC,
                                                       bv + l * HC, bs + l * HC, HC);
        gemm_tc_kernel<<<ggrid, 256, smemBytes>>>(hh, N_NODES, HC);
        attn_kernel<<<attnBlocks, 256>>>();
    }

    // pooling + fc
    zero_pool_kernel<<<(G_GRAPHS * HC + TB - 1) / TB, TB>>>();
    pool_kernel<<<256, 256>>>(batch);
    fc_kernel<<<G_GRAPHS, OUT_F>>>(Wfc, bfc, out);
}

// round 13
// speedup vs baseline: 1.1848x; 1.1848x over previous
#include <cuda_runtime.h>
#include <cuda_fp16.h>
#include <math.h>

#define N_NODES 50000
#define N_EDGES 800000
#define IN_F    128
#define HC      256
#define G_GRAPHS 64
#define OUT_F   64
#define NLAYERS 4
#define SCAN_BLOCKS ((N_NODES + 255) / 256)   // 196

// ---------------- scratch (static device allocations; no cudaMalloc) ----------------
__device__ float  g_qs[(size_t)N_NODES * 512];    // [q|s] per node, fp32
__device__ __half g_kv[(size_t)N_NODES * 512];    // [k|v] per node, fp16
__device__ __half g_hh[(size_t)N_NODES * HC];     // layer activations, fp16
__device__ __half g_xh[(size_t)N_NODES * IN_F];   // input x converted to fp16
__device__ __half g_Wc[1024 * 256];               // packed W^T [1024 cols][K], fp16
__device__ float  g_bc[1024];
__device__ int    g_cnt[N_NODES];
__device__ int    g_cur[N_NODES];
__device__ int    g_off[N_NODES + 1];
__device__ int    g_btot[256];
__device__ int    g_bbase[256];
__device__ int    g_psrc[N_EDGES];
__device__ float  g_pool[G_GRAPHS * HC];
__device__ int    g_gcnt[G_GRAPHS];

// ---------------- CSR build ----------------
__global__ void zero_csr_kernel() {
    int i = blockIdx.x * blockDim.x + threadIdx.x;
    if (i < N_NODES) { g_cnt[i] = 0; g_cur[i] = 0; }
}

__global__ void hist_kernel(const int* __restrict__ dst) {
    int e = blockIdx.x * blockDim.x + threadIdx.x;
    if (e < N_EDGES) atomicAdd(&g_cnt[dst[e]], 1);
}

// 3-phase scan: per-block exclusive scan + block totals
__global__ void scan1_kernel() {
    __shared__ int buf[256];
    int b = blockIdx.x, tid = threadIdx.x;
    int i = b * 256 + tid;
    int v = (i < N_NODES) ? g_cnt[i] : 0;
    buf[tid] = v;
    __syncthreads();
    #pragma unroll
    for (int ofs = 1; ofs < 256; ofs <<= 1) {
        int t = (tid >= ofs) ? buf[tid - ofs] : 0;
        __syncthreads();
        buf[tid] += t;
        __syncthreads();
    }
    if (i < N_NODES) g_off[i] = buf[tid] - v;
    if (tid == 255) g_btot[b] = buf[255];
}

__global__ void scan2_kernel() {
    __shared__ int buf[256];
    int tid = threadIdx.x;
    int v = (tid < SCAN_BLOCKS) ? g_btot[tid] : 0;
    buf[tid] = v;
    __syncthreads();
    #pragma unroll
    for (int ofs = 1; ofs < 256; ofs <<= 1) {
        int t = (tid >= ofs) ? buf[tid - ofs] : 0;
        __syncthreads();
        buf[tid] += t;
        __syncthreads();
    }
    g_bbase[tid] = buf[tid] - v;
}

__global__ void scan3_kernel() {
    int b = blockIdx.x, tid = threadIdx.x;
    int i = b * 256 + tid;
    if (i < N_NODES) g_off[i] += g_bbase[b];
    if (i == 0) g_off[N_NODES] = N_EDGES;
}

__global__ void scatter_kernel(const int* __restrict__ src, const int* __restrict__ dst) {
    int e = blockIdx.x * blockDim.x + threadIdx.x;
    if (e < N_EDGES) {
        int d = dst[e];
        int p = atomicAdd(&g_cur[d], 1);
        g_psrc[g_off[d] + p] = src[e];
    }
}

// ---------------- x -> fp16 conversion (once) ----------------
__global__ void xcvt_kernel(const float* __restrict__ x) {
    int i = blockIdx.x * blockDim.x + threadIdx.x;
    int total = N_NODES * IN_F / 2;
    if (i < total) {
        float2 v = *(const float2*)(x + (size_t)i * 2);
        *(__half2*)(g_xh + (size_t)i * 2) = __floats2half2_rn(v.x, v.y);
    }
}

// ---------------- weight packing: [F,256]x4 -> W^T [1024][F], fp16 ----------------
__global__ void pack_kernel(const float* __restrict__ Wq, const float* __restrict__ Wk,
                            const float* __restrict__ Wv, const float* __restrict__ Ws,
                            const float* __restrict__ bq, const float* __restrict__ bk,
                            const float* __restrict__ bv, const float* __restrict__ bs,
                            int F) {
    int idx = blockIdx.x * blockDim.x + threadIdx.x;
    int total = F * 1024;
    if (idx < total) {
        int f   = idx & (F - 1);
        int col = idx / F;
        int sel = col >> 8;
        int c   = col & 255;
        const float* W = (sel == 0) ? Wq : (sel == 1) ? Wk : (sel == 2) ? Wv : Ws;
        g_Wc[idx] = __float2half_rn(W[f * 256 + c]);
    }
    if (idx < 1024) {
        int sel = idx >> 8, c = idx & 255;
        const float* b = (sel == 0) ? bq : (sel == 1) ? bk : (sel == 2) ? bv : bs;
        g_bc[idx] = b[c];
    }
}

// ---------------- fp16 tensor-core GEMM: 128x128 tile, GBK=64, frag double-buffer ----------------
#define GBM 128
#define GBN 128
#define GBK 64
#define HPITCH 72     // 72 halfs = 144B pitch; ldmatrix rows hit banks 4r..4r+3 (conflict-free)
#define ABUF (GBM * HPITCH)                 // 9216 halfs
#define BBUF (GBN * HPITCH)                 // 9216 halfs
#define SMEM_BYTES ((2 * ABUF + 2 * BBUF) * 2)   // 73728 bytes

__device__ __forceinline__ void cp_async16(void* smem_dst, const void* gsrc, int src_bytes) {
    unsigned sdst = (unsigned)__cvta_generic_to_shared(smem_dst);
    asm volatile("cp.async.ca.shared.global [%0], [%1], 16, %2;"
                 :: "r"(sdst), "l"(gsrc), "r"(src_bytes));
}
__device__ __forceinline__ void cp_async_commit() {
    asm volatile("cp.async.commit_group;");
}
template <int NN>
__device__ __forceinline__ void cp_async_wait() {
    asm volatile("cp.async.wait_group %0;" :: "n"(NN));
}

__device__ __forceinline__ void ldsm_x4(unsigned& r0, unsigned& r1, unsigned& r2, unsigned& r3,
                                        unsigned addr) {
    asm volatile("ldmatrix.sync.aligned.m8n8.x4.shared.b16 {%0,%1,%2,%3}, [%4];"
                 : "=r"(r0), "=r"(r1), "=r"(r2), "=r"(r3) : "r"(addr));
}
__device__ __forceinline__ void ldsm_x2(unsigned& r0, unsigned& r1, unsigned addr) {
    asm volatile("ldmatrix.sync.aligned.m8n8.x2.shared.b16 {%0,%1}, [%2];"
                 : "=r"(r0), "=r"(r1) : "r"(addr));
}

__device__ __forceinline__ void store_seg(int row, int col, float vx, float vy) {
    if (col < 256) {
        *(float2*)(g_qs + (size_t)row * 512 + col) = make_float2(vx, vy);
    } else if (col < 768) {
        *(__half2*)(g_kv + (size_t)row * 512 + (col - 256)) = __floats2half2_rn(vx, vy);
    } else {
        *(float2*)(g_qs + (size_t)row * 512 + 256 + (col - 768)) = make_float2(vx, vy);
    }
}

__global__ __launch_bounds__(256, 2) void gemm_tc_kernel(const __half* __restrict__ A, int M, int K) {
    extern __shared__ __half sm[];
    __half* AsBuf[2] = { sm, sm + ABUF };
    __half* BsBuf[2] = { sm + 2 * ABUF, sm + 2 * ABUF + BBUF };

    int tid  = threadIdx.x;
    int lane = tid & 31;
    int wid  = tid >> 5;
    int gid  = lane >> 2;
    int tig  = lane & 3;
    int warpM = wid & 1;    // 64 rows each
    int warpN = wid >> 1;   // 32 cols each

    int mBase = blockIdx.y * GBM;
    int nBase = blockIdx.x * GBN;

    // ldmatrix per-thread offsets (R10-verified mappings)
    int aRowOff = lane & 15;
    int aKOff   = (lane >> 4) << 3;        // 0 or 8
    int bColOff = lane & 7;
    int bKOff   = ((lane >> 3) & 1) << 3;  // 0 or 8

    float c[4][4][4];
    #pragma unroll
    for (int i = 0; i < 4; i++)
        #pragma unroll
        for (int j = 0; j < 4; j++)
            #pragma unroll
            for (int r = 0; r < 4; r++) c[i][j][r] = 0.f;

    int nTiles = K / GBK;

    // cp.async tile loader: A/B each 128 rows x 8 16B-chunks = 1024 chunks -> 4 per thread
    auto load_tile = [&](int bufIdx, int k0) {
        __half* As = AsBuf[bufIdx];
        __half* Bs = BsBuf[bufIdx];
        #pragma unroll
        for (int t = 0; t < 4; t++) {
            int idx = tid + t * 256;
            int row = idx >> 3;
            int ck  = idx & 7;
            int gm  = mBase + row;
            int ok  = (gm < M) ? 16 : 0;
            const __half* srcA = A + (size_t)((gm < M) ? gm : 0) * K + k0 + ck * 8;
            cp_async16(&As[row * HPITCH + ck * 8], srcA, ok);
            const __half* srcB = g_Wc + (size_t)(nBase + row) * K + k0 + ck * 8;
            cp_async16(&Bs[row * HPITCH + ck * 8], srcB, 16);
        }
        cp_async_commit();
    };

    load_tile(0, 0);

    unsigned af[2][4][4];
    unsigned bf[2][4][2];

    for (int kt = 0; kt < nTiles; kt++) {
        int buf = kt & 1;
        if (kt + 1 < nTiles) {
            load_tile(buf ^ 1, (kt + 1) * GBK);
            cp_async_wait<1>();
        } else {
            cp_async_wait<0>();
        }
        __syncthreads();

        unsigned asb = (unsigned)__cvta_generic_to_shared(AsBuf[buf]);
        unsigned bsb = (unsigned)__cvta_generic_to_shared(BsBuf[buf]);

        // fragment loader for one ks step into register set s
        auto load_frags = [&](int s, int kk) {
            #pragma unroll
            for (int mt = 0; mt < 4; mt++) {
                unsigned addr = asb +
                    ((warpM * 64 + mt * 16 + aRowOff) * HPITCH + kk + aKOff) * 2;
                ldsm_x4(af[s][mt][0], af[s][mt][1], af[s][mt][2], af[s][mt][3], addr);
            }
            #pragma unroll
            for (int nt = 0; nt < 4; nt++) {
                unsigned addr = bsb +
                    ((warpN * 32 + nt * 8 + bColOff) * HPITCH + kk + bKOff) * 2;
                ldsm_x2(bf[s][nt][0], bf[s][nt][1], addr);
            }
        };

        load_frags(0, 0);
        #pragma unroll
        for (int ks = 0; ks < 4; ks++) {
            int cur = ks & 1;
            if (ks < 3) load_frags(cur ^ 1, (ks + 1) * 16);
            #pragma unroll
            for (int mt = 0; mt < 4; mt++)
                #pragma unroll
                for (int nt = 0; nt < 4; nt++) {
                    asm volatile(
                        "mma.sync.aligned.m16n8k16.row.col.f32.f16.f16.f32 "
                        "{%0,%1,%2,%3}, {%4,%5,%6,%7}, {%8,%9}, {%0,%1,%2,%3};"
                        : "+f"(c[mt][nt][0]), "+f"(c[mt][nt][1]),
                          "+f"(c[mt][nt][2]), "+f"(c[mt][nt][3])
                        : "r"(af[cur][mt][0]), "r"(af[cur][mt][1]),
                          "r"(af[cur][mt][2]), "r"(af[cur][mt][3]),
                          "r"(bf[cur][nt][0]), "r"(bf[cur][nt][1]));
                }
        }
        __syncthreads();
    }

    // epilogue: bias + routed store
    #pragma unroll
    for (int nt = 0; nt < 4; nt++) {
        int col = nBase + warpN * 32 + nt * 8 + tig * 2;
        float2 bias = *(const float2*)(g_bc + col);
        #pragma unroll
        for (int mt = 0; mt < 4; mt++) {
            int row0 = mBase + warpM * 64 + mt * 16 + gid;
            if (row0 < M)
                store_seg(row0, col, c[mt][nt][0] + bias.x, c[mt][nt][1] + bias.y);
            int row1 = row0 + 8;
            if (row1 < M)
                store_seg(row1, col, c[mt][nt][2] + bias.x, c[mt][nt][3] + bias.y);
        }
    }
}

// ---------------- attention: one warp per dst node, depth-2 index prefetch ----------------
__global__ __launch_bounds__(256) void attn_kernel() {
    int warp = (blockIdx.x * blockDim.x + threadIdx.x) >> 5;
    int lane = threadIdx.x & 31;
    if (warp >= N_NODES) return;

    const float* base_q = g_qs + (size_t)warp * 512 + lane * 8;
    float4 q0 = *(const float4*)(base_q);
    float4 q1 = *(const float4*)(base_q + 4);

    float m = -INFINITY, s = 0.f;
    float4 a0 = make_float4(0.f, 0.f, 0.f, 0.f);
    float4 a1 = make_float4(0.f, 0.f, 0.f, 0.f);

    int e0 = g_off[warp], e1 = g_off[warp + 1];

    uint4 kc = make_uint4(0, 0, 0, 0), vc = make_uint4(0, 0, 0, 0);
    int sB = 0;
    if (e0 < e1) {
        const __half* kvb = g_kv + (size_t)g_psrc[e0] * 512 + lane * 8;
        kc = *(const uint4*)(kvb);
        vc = *(const uint4*)(kvb + 256);
        if (e0 + 1 < e1) sB = g_psrc[e0 + 1];
    }

    for (int i = e0; i < e1; i++) {
        uint4 kcur = kc, vcur = vc;
        int sC = (i + 2 < e1) ? g_psrc[i + 2] : 0;
        if (i + 1 < e1) {
            const __half* kvb = g_kv + (size_t)sB * 512 + lane * 8;
            kc = *(const uint4*)(kvb);
            vc = *(const uint4*)(kvb + 256);
        }
        sB = sC;

        float2 k01 = __half22float2(*(const __half2*)&kcur.x);
        float2 k23 = __half22float2(*(const __half2*)&kcur.y);
        float2 k45 = __half22float2(*(const __half2*)&kcur.z);
        float2 k67 = __half22float2(*(const __half2*)&kcur.w);

        float d = q0.x * k01.x + q0.y * k01.y + q0.z * k23.x + q0.w * k23.y
                + q1.x * k45.x + q1.y * k45.y + q1.z * k67.x + q1.w * k67.y;
        d += __shfl_xor_sync(0xFFFFFFFFu, d, 1);
        d += __shfl_xor_sync(0xFFFFFFFFu, d, 2);
        float logit = d * 0.17677669529663687f;   // 1/sqrt(32)

        float mN = fmaxf(m, logit);
        float sc = __expf(m - mN);
        float p  = __expf(logit - mN);
        m = mN;
        s = s * sc + p;

        float2 v01 = __half22float2(*(const __half2*)&vcur.x);
        float2 v23 = __half22float2(*(const __half2*)&vcur.y);
        float2 v45 = __half22float2(*(const __half2*)&vcur.z);
        float2 v67 = __half22float2(*(const __half2*)&vcur.w);

        a0.x = a0.x * sc + p * v01.x; a0.y = a0.y * sc + p * v01.y;
        a0.z = a0.z * sc + p * v23.x; a0.w = a0.w * sc + p * v23.y;
        a1.x = a1.x * sc + p * v45.x; a1.y = a1.y * sc + p * v45.y;
        a1.z = a1.z * sc + p * v67.x; a1.w = a1.w * sc + p * v67.y;
    }

    float inv = 1.f / (s + 1e-16f);
    const float* sb = g_qs + (size_t)warp * 512 + 256 + lane * 8;
    float4 s0 = *(const float4*)(sb);
    float4 s1 = *(const float4*)(sb + 4);
    float r0 = fmaxf(a0.x * inv + s0.x, 0.f);
    float r1 = fmaxf(a0.y * inv + s0.y, 0.f);
    float r2 = fmaxf(a0.z * inv + s0.z, 0.f);
    float r3 = fmaxf(a0.w * inv + s0.w, 0.f);
    float r4 = fmaxf(a1.x * inv + s1.x, 0.f);
    float r5 = fmaxf(a1.y * inv + s1.y, 0.f);
    float r6 = fmaxf(a1.z * inv + s1.z, 0.f);
    float r7 = fmaxf(a1.w * inv + s1.w, 0.f);

    __half* hb = g_hh + (size_t)warp * 256 + lane * 8;
    uint4 packed;
    *(__half2*)&packed.x = __floats2half2_rn(r0, r1);
    *(__half2*)&packed.y = __floats2half2_rn(r2, r3);
    *(__half2*)&packed.z = __floats2half2_rn(r4, r5);
    *(__half2*)&packed.w = __floats2half2_rn(r6, r7);
    *(uint4*)hb = packed;
}

// ---------------- pooling ----------------
__global__ void zero_pool_kernel() {
    int i = blockIdx.x * blockDim.x + threadIdx.x;
    if (i < G_GRAPHS * HC) g_pool[i] = 0.f;
    if (i < G_GRAPHS) g_gcnt[i] = 0;
}

__global__ __launch_bounds__(256) void pool_kernel(const int* __restrict__ batch) {
    int c = threadIdx.x;
    int per = (N_NODES + gridDim.x - 1) / gridDim.x;
    int start = blockIdx.x * per;
    int end = min(N_NODES, start + per);
    if (start >= end) return;
    int cur = batch[start];
    float acc = 0.f;
    int cnt = 0;
    for (int i = start; i < end; i++) {
        int b = batch[i];
        if (b != cur) {
            atomicAdd(&g_pool[cur * HC + c], acc);
            if (c == 0) atomicAdd(&g_gcnt[cur], cnt);
            acc = 0.f; cnt = 0; cur = b;
        }
        acc += __half2float(g_hh[(size_t)i * HC + c]);
        cnt++;
    }
    atomicAdd(&g_pool[cur * HC + c], acc);
    if (c == 0) atomicAdd(&g_gcnt[cur], cnt);
}

__global__ void fc_kernel(const float* __restrict__ Wfc, const float* __restrict__ bfc,
                          float* __restrict__ out) {
    int g = blockIdx.x;
    int o = threadIdx.x;
    __shared__ float p[HC];
    float inv = 1.f / fmaxf((float)g_gcnt[g], 1.f);
    for (int i = o; i < HC; i += OUT_F) p[i] = g_pool[g * HC + i] * inv;
    __syncthreads();
    float acc = bfc[o];
    #pragma unroll 8
    for (int f = 0; f < HC; f++) acc += p[f] * Wfc[f * OUT_F + o];
    out[g * OUT_F + o] = acc;
}

// ---------------- launch ----------------
extern "C" void kernel_launch(void* const* d_in, const int* in_sizes, int n_in,
                              void* d_out, int out_size) {
    const float* x    = (const float*)d_in[0];
    const int*   ei   = (const int*)d_in[1];
    const int*   src  = ei;
    const int*   dst  = ei + N_EDGES;
    const int*   batch = (const int*)d_in[2];
    const float* Wq0 = (const float*)d_in[3];
    const float* bq0 = (const float*)d_in[4];
    const float* Wk0 = (const float*)d_in[5];
    const float* bk0 = (const float*)d_in[6];
    const float* Wv0 = (const float*)d_in[7];
    const float* bv0 = (const float*)d_in[8];
    const float* Ws0 = (const float*)d_in[9];
    const float* bs0 = (const float*)d_in[10];
    const float* Wq  = (const float*)d_in[11];
    const float* bq  = (const float*)d_in[12];
    const float* Wk  = (const float*)d_in[13];
    const float* bk  = (const float*)d_in[14];
    const float* Wv  = (const float*)d_in[15];
    const float* bv  = (const float*)d_in[16];
    const float* Ws  = (const float*)d_in[17];
    const float* bs  = (const float*)d_in[18];
    const float* Wfc = (const float*)d_in[19];
    const float* bfc = (const float*)d_in[20];
    float* out = (float*)d_out;

    const int TB = 256;
    dim3 ggrid(1024 / GBN, (N_NODES + GBM - 1) / GBM);   // (8, 391)
    int attnBlocks = (N_NODES + 7) / 8;

    __half* xh = nullptr;
    __half* hh = nullptr;
    cudaGetSymbolAddress((void**)&xh, g_xh);
    cudaGetSymbolAddress((void**)&hh, g_hh);

    cudaFuncSetAttribute(gemm_tc_kernel, cudaFuncAttributeMaxDynamicSharedMemorySize, SMEM_BYTES);

    // gemm_tc_kernel is the 4th launch (ncu capture slot).
    xcvt_kernel<<<(N_NODES * IN_F / 2 + TB - 1) / TB, TB>>>(x);                              // 1
    pack_kernel<<<(IN_F * 1024 + TB - 1) / TB, TB>>>(Wq0, Wk0, Wv0, Ws0,
                                                     bq0, bk0, bv0, bs0, IN_F);              // 2
    zero_csr_kernel<<<(N_NODES + TB - 1) / TB, TB>>>();                                      // 3
    gemm_tc_kernel<<<ggrid, 256, SMEM_BYTES>>>(xh, N_NODES, IN_F);                           // 4 (profiled)
    hist_kernel<<<(N_EDGES + TB - 1) / TB, TB>>>(dst);                                       // 5
    scan1_kernel<<<SCAN_BLOCKS, 256>>>();                                                    // 6
    scan2_kernel<<<1, 256>>>();                                                              // 7
    scan3_kernel<<<SCAN_BLOCKS, 256>>>();                                                    // 8
    scatter_kernel<<<(N_EDGES + TB - 1) / TB, TB>>>(src, dst);                               // 9
    attn_kernel<<<attnBlocks, 256>>>();                                                      // 10

    // layers 1..3 (HC -> HC)
    for (int l = 0; l < NLAYERS - 1; l++) {
        const float* wq = Wq + (size_t)l * HC * HC;
        const float* wk = Wk + (size_t)l * HC * HC;
        const float* wv = Wv + (size_t)l * HC * HC;
        const float* ws = Ws + (size_t)l * HC * HC;
        pack_kernel<<<(HC * 1024 + TB - 1) / TB, TB>>>(wq, wk, wv, ws,
                                                       bq + l * HC, bk + l * HC,
                                                       bv + l * HC, bs + l * HC, HC);
        gemm_tc_kernel<<<ggrid, 256, SMEM_BYTES>>>(hh, N_NODES, HC);
        attn_kernel<<<attnBlocks, 256>>>();
    }

    // pooling + fc
    zero_pool_kernel<<<(G_GRAPHS * HC + TB - 1) / TB, TB>>>();
    pool_kernel<<<256, 256>>>(batch);
    fc_kernel<<<G_GRAPHS, OUT_F>>>(Wfc, bfc, out);
}

// round 14
// speedup vs baseline: 1.2025x; 1.0149x over previous
#include <cuda_runtime.h>
#include <cuda_fp16.h>
#include <math.h>

#define N_NODES 50000
#define N_EDGES 800000
#define IN_F    128
#define HC      256
#define G_GRAPHS 64
#define OUT_F   64
#define NLAYERS 4
#define SCAN_BLOCKS ((N_NODES + 255) / 256)   // 196

// ---------------- scratch (static device allocations; no cudaMalloc) ----------------
__device__ float  g_qs[(size_t)N_NODES * 512];    // [q|s] per node, fp32
__device__ __half g_kv[(size_t)N_NODES * 512];    // [k|v] per node, fp16
__device__ __half g_hh[(size_t)N_NODES * HC];     // layer activations, fp16
__device__ __half g_xh[(size_t)N_NODES * IN_F];   // input x converted to fp16
__device__ __half g_Wc[1024 * 256];               // packed W^T [1024 cols][K], fp16
__device__ float  g_bc[1024];
__device__ int    g_cnt[N_NODES];
__device__ int    g_cur[N_NODES];
__device__ int    g_off[N_NODES + 1];
__device__ int    g_btot[256];
__device__ int    g_bbase[256];
__device__ int    g_psrc[N_EDGES];
__device__ float  g_pool[G_GRAPHS * HC];
__device__ int    g_gcnt[G_GRAPHS];

// ---------------- x -> fp16 conversion + CSR zero (fused) ----------------
__global__ void xcvt_kernel(const float* __restrict__ x) {
    int i = blockIdx.x * blockDim.x + threadIdx.x;
    int total = N_NODES * IN_F / 2;
    if (i < total) {
        float2 v = *(const float2*)(x + (size_t)i * 2);
        *(__half2*)(g_xh + (size_t)i * 2) = __floats2half2_rn(v.x, v.y);
    }
    if (i < N_NODES) { g_cnt[i] = 0; g_cur[i] = 0; }
}

__global__ void hist_kernel(const int* __restrict__ dst) {
    int e = blockIdx.x * blockDim.x + threadIdx.x;
    if (e < N_EDGES) atomicAdd(&g_cnt[dst[e]], 1);
}

// 3-phase scan
__global__ void scan1_kernel() {
    __shared__ int buf[256];
    int b = blockIdx.x, tid = threadIdx.x;
    int i = b * 256 + tid;
    int v = (i < N_NODES) ? g_cnt[i] : 0;
    buf[tid] = v;
    __syncthreads();
    #pragma unroll
    for (int ofs = 1; ofs < 256; ofs <<= 1) {
        int t = (tid >= ofs) ? buf[tid - ofs] : 0;
        __syncthreads();
        buf[tid] += t;
        __syncthreads();
    }
    if (i < N_NODES) g_off[i] = buf[tid] - v;
    if (tid == 255) g_btot[b] = buf[255];
}

__global__ void scan2_kernel() {
    __shared__ int buf[256];
    int tid = threadIdx.x;
    int v = (tid < SCAN_BLOCKS) ? g_btot[tid] : 0;
    buf[tid] = v;
    __syncthreads();
    #pragma unroll
    for (int ofs = 1; ofs < 256; ofs <<= 1) {
        int t = (tid >= ofs) ? buf[tid - ofs] : 0;
        __syncthreads();
        buf[tid] += t;
        __syncthreads();
    }
    g_bbase[tid] = buf[tid] - v;
}

// scan3 + pool-zero (fused)
__global__ void scan3_kernel() {
    int b = blockIdx.x, tid = threadIdx.x;
    int i = b * 256 + tid;
    if (i < N_NODES) g_off[i] += g_bbase[b];
    if (i == 0) g_off[N_NODES] = N_EDGES;
    if (i < G_GRAPHS * HC) g_pool[i] = 0.f;
    if (i < G_GRAPHS) g_gcnt[i] = 0;
}

__global__ void scatter_kernel(const int* __restrict__ src, const int* __restrict__ dst) {
    int e = blockIdx.x * blockDim.x + threadIdx.x;
    if (e < N_EDGES) {
        int d = dst[e];
        int p = atomicAdd(&g_cur[d], 1);
        g_psrc[g_off[d] + p] = src[e];
    }
}

// ---------------- weight packing: [F,256]x4 -> W^T [1024][F], fp16 ----------------
__global__ void pack_kernel(const float* __restrict__ Wq, const float* __restrict__ Wk,
                            const float* __restrict__ Wv, const float* __restrict__ Ws,
                            const float* __restrict__ bq, const float* __restrict__ bk,
                            const float* __restrict__ bv, const float* __restrict__ bs,
                            int F) {
    int idx = blockIdx.x * blockDim.x + threadIdx.x;
    int total = F * 1024;
    if (idx < total) {
        int f   = idx & (F - 1);
        int col = idx / F;
        int sel = col >> 8;
        int c   = col & 255;
        const float* W = (sel == 0) ? Wq : (sel == 1) ? Wk : (sel == 2) ? Wv : Ws;
        g_Wc[idx] = __float2half_rn(W[f * 256 + c]);
    }
    if (idx < 1024) {
        int sel = idx >> 8, c = idx & 255;
        const float* b = (sel == 0) ? bq : (sel == 1) ? bk : (sel == 2) ? bv : bs;
        g_bc[idx] = b[c];
    }
}

// ---------------- fp16 tensor-core GEMM: 128x128 tile, GBK=64, 1 barrier/tile ----------------
#define GBM 128
#define GBN 128
#define GBK 64
#define HPITCH 72
#define ABUF (GBM * HPITCH)
#define BBUF (GBN * HPITCH)
#define SMEM_BYTES ((2 * ABUF + 2 * BBUF) * 2)   // 73728 bytes

__device__ __forceinline__ void cp_async16(void* smem_dst, const void* gsrc, int src_bytes) {
    unsigned sdst = (unsigned)__cvta_generic_to_shared(smem_dst);
    asm volatile("cp.async.ca.shared.global [%0], [%1], 16, %2;"
                 :: "r"(sdst), "l"(gsrc), "r"(src_bytes));
}
__device__ __forceinline__ void cp_async_commit() {
    asm volatile("cp.async.commit_group;");
}
template <int NN>
__device__ __forceinline__ void cp_async_wait() {
    asm volatile("cp.async.wait_group %0;" :: "n"(NN));
}

__device__ __forceinline__ void ldsm_x4(unsigned& r0, unsigned& r1, unsigned& r2, unsigned& r3,
                                        unsigned addr) {
    asm volatile("ldmatrix.sync.aligned.m8n8.x4.shared.b16 {%0,%1,%2,%3}, [%4];"
                 : "=r"(r0), "=r"(r1), "=r"(r2), "=r"(r3) : "r"(addr));
}
__device__ __forceinline__ void ldsm_x2(unsigned& r0, unsigned& r1, unsigned addr) {
    asm volatile("ldmatrix.sync.aligned.m8n8.x2.shared.b16 {%0,%1}, [%2];"
                 : "=r"(r0), "=r"(r1) : "r"(addr));
}

__device__ __forceinline__ void store_seg(int row, int col, float vx, float vy) {
    if (col < 256) {
        *(float2*)(g_qs + (size_t)row * 512 + col) = make_float2(vx, vy);
    } else if (col < 768) {
        *(__half2*)(g_kv + (size_t)row * 512 + (col - 256)) = __floats2half2_rn(vx, vy);
    } else {
        *(float2*)(g_qs + (size_t)row * 512 + 256 + (col - 768)) = make_float2(vx, vy);
    }
}

__global__ __launch_bounds__(256, 2) void gemm_tc_kernel(const __half* __restrict__ A, int M, int K) {
    extern __shared__ __half sm[];
    __half* AsBuf[2] = { sm, sm + ABUF };
    __half* BsBuf[2] = { sm + 2 * ABUF, sm + 2 * ABUF + BBUF };

    int tid  = threadIdx.x;
    int lane = tid & 31;
    int wid  = tid >> 5;
    int gid  = lane >> 2;
    int tig  = lane & 3;
    int warpM = wid & 1;
    int warpN = wid >> 1;

    int mBase = blockIdx.y * GBM;
    int nBase = blockIdx.x * GBN;

    // hoisted per-thread fragment byte offsets (relative to buffer base)
    int aRowOff = lane & 15;
    int aKOff   = (lane >> 4) << 3;
    int bColOff = lane & 7;
    int bKOff   = ((lane >> 3) & 1) << 3;
    unsigned aOff[4], bOff[4];
    #pragma unroll
    for (int mt = 0; mt < 4; mt++)
        aOff[mt] = ((warpM * 64 + mt * 16 + aRowOff) * HPITCH + aKOff) * 2;
    #pragma unroll
    for (int nt = 0; nt < 4; nt++)
        bOff[nt] = ((warpN * 32 + nt * 8 + bColOff) * HPITCH + bKOff) * 2;
    unsigned asbB[2] = { (unsigned)__cvta_generic_to_shared(AsBuf[0]),
                         (unsigned)__cvta_generic_to_shared(AsBuf[1]) };
    unsigned bsbB[2] = { (unsigned)__cvta_generic_to_shared(BsBuf[0]),
                         (unsigned)__cvta_generic_to_shared(BsBuf[1]) };

    float c[4][4][4];
    #pragma unroll
    for (int i = 0; i < 4; i++)
        #pragma unroll
        for (int j = 0; j < 4; j++)
            #pragma unroll
            for (int r = 0; r < 4; r++) c[i][j][r] = 0.f;

    int nTiles = K / GBK;

    auto load_tile = [&](int bufIdx, int k0) {
        __half* As = AsBuf[bufIdx];
        __half* Bs = BsBuf[bufIdx];
        #pragma unroll
        for (int t = 0; t < 4; t++) {
            int idx = tid + t * 256;
            int row = idx >> 3;
            int ck  = idx & 7;
            int gm  = mBase + row;
            int ok  = (gm < M) ? 16 : 0;
            const __half* srcA = A + (size_t)((gm < M) ? gm : 0) * K + k0 + ck * 8;
            cp_async16(&As[row * HPITCH + ck * 8], srcA, ok);
            const __half* srcB = g_Wc + (size_t)(nBase + row) * K + k0 + ck * 8;
            cp_async16(&Bs[row * HPITCH + ck * 8], srcB, 16);
        }
        cp_async_commit();
    };

    load_tile(0, 0);

    unsigned af[2][4][4];
    unsigned bf[2][4][2];

    for (int kt = 0; kt < nTiles; kt++) {
        int buf = kt & 1;
        // single barrier per tile: wait for load(kt), sync, then issue load(kt+1).
        // load(kt+1) overwrites the buffer last read by compute(kt-1), which all
        // warps finished before this barrier.
        cp_async_wait<0>();
        __syncthreads();
        if (kt + 1 < nTiles) load_tile(buf ^ 1, (kt + 1) * GBK);

        unsigned asb = asbB[buf];
        unsigned bsb = bsbB[buf];

        auto load_frags = [&](int s, int kk) {
            unsigned kByte = (unsigned)(kk * 2);
            #pragma unroll
            for (int mt = 0; mt < 4; mt++)
                ldsm_x4(af[s][mt][0], af[s][mt][1], af[s][mt][2], af[s][mt][3],
                        asb + aOff[mt] + kByte);
            #pragma unroll
            for (int nt = 0; nt < 4; nt++)
                ldsm_x2(bf[s][nt][0], bf[s][nt][1], bsb + bOff[nt] + kByte);
        };

        load_frags(0, 0);
        #pragma unroll
        for (int ks = 0; ks < 4; ks++) {
            int cur = ks & 1;
            if (ks < 3) load_frags(cur ^ 1, (ks + 1) * 16);
            #pragma unroll
            for (int mt = 0; mt < 4; mt++)
                #pragma unroll
                for (int nt = 0; nt < 4; nt++) {
                    asm volatile(
                        "mma.sync.aligned.m16n8k16.row.col.f32.f16.f16.f32 "
                        "{%0,%1,%2,%3}, {%4,%5,%6,%7}, {%8,%9}, {%0,%1,%2,%3};"
                        : "+f"(c[mt][nt][0]), "+f"(c[mt][nt][1]),
                          "+f"(c[mt][nt][2]), "+f"(c[mt][nt][3])
                        : "r"(af[cur][mt][0]), "r"(af[cur][mt][1]),
                          "r"(af[cur][mt][2]), "r"(af[cur][mt][3]),
                          "r"(bf[cur][nt][0]), "r"(bf[cur][nt][1]));
                }
        }
    }

    // epilogue: bias + routed store
    #pragma unroll
    for (int nt = 0; nt < 4; nt++) {
        int col = nBase + warpN * 32 + nt * 8 + tig * 2;
        float2 bias = *(const float2*)(g_bc + col);
        #pragma unroll
        for (int mt = 0; mt < 4; mt++) {
            int row0 = mBase + warpM * 64 + mt * 16 + gid;
            if (row0 < M)
                store_seg(row0, col, c[mt][nt][0] + bias.x, c[mt][nt][1] + bias.y);
            int row1 = row0 + 8;
            if (row1 < M)
                store_seg(row1, col, c[mt][nt][2] + bias.x, c[mt][nt][3] + bias.y);
        }
    }
}

// ---------------- attention: one warp per dst node, depth-2 index prefetch ----------------
__global__ __launch_bounds__(256) void attn_kernel() {
    int warp = (blockIdx.x * blockDim.x + threadIdx.x) >> 5;
    int lane = threadIdx.x & 31;
    if (warp >= N_NODES) return;

    const float* base_q = g_qs + (size_t)warp * 512 + lane * 8;
    float4 q0 = *(const float4*)(base_q);
    float4 q1 = *(const float4*)(base_q + 4);

    float m = -INFINITY, s = 0.f;
    float4 a0 = make_float4(0.f, 0.f, 0.f, 0.f);
    float4 a1 = make_float4(0.f, 0.f, 0.f, 0.f);

    int e0 = g_off[warp], e1 = g_off[warp + 1];

    uint4 kc = make_uint4(0, 0, 0, 0), vc = make_uint4(0, 0, 0, 0);
    int sB = 0;
    if (e0 < e1) {
        const __half* kvb = g_kv + (size_t)g_psrc[e0] * 512 + lane * 8;
        kc = *(const uint4*)(kvb);
        vc = *(const uint4*)(kvb + 256);
        if (e0 + 1 < e1) sB = g_psrc[e0 + 1];
    }

    for (int i = e0; i < e1; i++) {
        uint4 kcur = kc, vcur = vc;
        int sC = (i + 2 < e1) ? g_psrc[i + 2] : 0;
        if (i + 1 < e1) {
            const __half* kvb = g_kv + (size_t)sB * 512 + lane * 8;
            kc = *(const uint4*)(kvb);
            vc = *(const uint4*)(kvb + 256);
        }
        sB = sC;

        float2 k01 = __half22float2(*(const __half2*)&kcur.x);
        float2 k23 = __half22float2(*(const __half2*)&kcur.y);
        float2 k45 = __half22float2(*(const __half2*)&kcur.z);
        float2 k67 = __half22float2(*(const __half2*)&kcur.w);

        float d = q0.x * k01.x + q0.y * k01.y + q0.z * k23.x + q0.w * k23.y
                + q1.x * k45.x + q1.y * k45.y + q1.z * k67.x + q1.w * k67.y;
        d += __shfl_xor_sync(0xFFFFFFFFu, d, 1);
        d += __shfl_xor_sync(0xFFFFFFFFu, d, 2);
        float logit = d * 0.17677669529663687f;   // 1/sqrt(32)

        float mN = fmaxf(m, logit);
        float sc = __expf(m - mN);
        float p  = __expf(logit - mN);
        m = mN;
        s = s * sc + p;

        float2 v01 = __half22float2(*(const __half2*)&vcur.x);
        float2 v23 = __half22float2(*(const __half2*)&vcur.y);
        float2 v45 = __half22float2(*(const __half2*)&vcur.z);
        float2 v67 = __half22float2(*(const __half2*)&vcur.w);

        a0.x = a0.x * sc + p * v01.x; a0.y = a0.y * sc + p * v01.y;
        a0.z = a0.z * sc + p * v23.x; a0.w = a0.w * sc + p * v23.y;
        a1.x = a1.x * sc + p * v45.x; a1.y = a1.y * sc + p * v45.y;
        a1.z = a1.z * sc + p * v67.x; a1.w = a1.w * sc + p * v67.y;
    }

    float inv = 1.f / (s + 1e-16f);
    const float* sb = g_qs + (size_t)warp * 512 + 256 + lane * 8;
    float4 s0 = *(const float4*)(sb);
    float4 s1 = *(const float4*)(sb + 4);
    float r0 = fmaxf(a0.x * inv + s0.x, 0.f);
    float r1 = fmaxf(a0.y * inv + s0.y, 0.f);
    float r2 = fmaxf(a0.z * inv + s0.z, 0.f);
    float r3 = fmaxf(a0.w * inv + s0.w, 0.f);
    float r4 = fmaxf(a1.x * inv + s1.x, 0.f);
    float r5 = fmaxf(a1.y * inv + s1.y, 0.f);
    float r6 = fmaxf(a1.z * inv + s1.z, 0.f);
    float r7 = fmaxf(a1.w * inv + s1.w, 0.f);

    __half* hb = g_hh + (size_t)warp * 256 + lane * 8;
    uint4 packed;
    *(__half2*)&packed.x = __floats2half2_rn(r0, r1);
    *(__half2*)&packed.y = __floats2half2_rn(r2, r3);
    *(__half2*)&packed.z = __floats2half2_rn(r4, r5);
    *(__half2*)&packed.w = __floats2half2_rn(r6, r7);
    *(uint4*)hb = packed;
}

// ---------------- pooling ----------------
__global__ __launch_bounds__(256) void pool_kernel(const int* __restrict__ batch) {
    int c = threadIdx.x;
    int per = (N_NODES + gridDim.x - 1) / gridDim.x;
    int start = blockIdx.x * per;
    int end = min(N_NODES, start + per);
    if (start >= end) return;
    int cur = batch[start];
    float acc = 0.f;
    int cnt = 0;
    for (int i = start; i < end; i++) {
        int b = batch[i];
        if (b != cur) {
            atomicAdd(&g_pool[cur * HC + c], acc);
            if (c == 0) atomicAdd(&g_gcnt[cur], cnt);
            acc = 0.f; cnt = 0; cur = b;
        }
        acc += __half2float(g_hh[(size_t)i * HC + c]);
        cnt++;
    }
    atomicAdd(&g_pool[cur * HC + c], acc);
    if (c == 0) atomicAdd(&g_gcnt[cur], cnt);
}

__global__ void fc_kernel(const float* __restrict__ Wfc, const float* __restrict__ bfc,
                          float* __restrict__ out) {
    int g = blockIdx.x;
    int o = threadIdx.x;
    __shared__ float p[HC];
    float inv = 1.f / fmaxf((float)g_gcnt[g], 1.f);
    for (int i = o; i < HC; i += OUT_F) p[i] = g_pool[g * HC + i] * inv;
    __syncthreads();
    float acc = bfc[o];
    #pragma unroll 8
    for (int f = 0; f < HC; f++) acc += p[f] * Wfc[f * OUT_F + o];
    out[g * OUT_F + o] = acc;
}

// ---------------- launch ----------------
extern "C" void kernel_launch(void* const* d_in, const int* in_sizes, int n_in,
                              void* d_out, int out_size) {
    const float* x    = (const float*)d_in[0];
    const int*   ei   = (const int*)d_in[1];
    const int*   src  = ei;
    const int*   dst  = ei + N_EDGES;
    const int*   batch = (const int*)d_in[2];
    const float* Wq0 = (const float*)d_in[3];
    const float* bq0 = (const float*)d_in[4];
    const float* Wk0 = (const float*)d_in[5];
    const float* bk0 = (const float*)d_in[6];
    const float* Wv0 = (const float*)d_in[7];
    const float* bv0 = (const float*)d_in[8];
    const float* Ws0 = (const float*)d_in[9];
    const float* bs0 = (const float*)d_in[10];
    const float* Wq  = (const float*)d_in[11];
    const float* bq  = (const float*)d_in[12];
    const float* Wk  = (const float*)d_in[13];
    const float* bk  = (const float*)d_in[14];
    const float* Wv  = (const float*)d_in[15];
    const float* bv  = (const float*)d_in[16];
    const float* Ws  = (const float*)d_in[17];
    const float* bs  = (const float*)d_in[18];
    const float* Wfc = (const float*)d_in[19];
    const float* bfc = (const float*)d_in[20];
    float* out = (float*)d_out;

    const int TB = 256;
    dim3 ggrid(1024 / GBN, (N_NODES + GBM - 1) / GBM);   // (8, 391)
    int attnBlocks = (N_NODES + 7) / 8;

    __half* xh = nullptr;
    __half* hh = nullptr;
    cudaGetSymbolAddress((void**)&xh, g_xh);
    cudaGetSymbolAddress((void**)&hh, g_hh);

    cudaFuncSetAttribute(gemm_tc_kernel, cudaFuncAttributeMaxDynamicSharedMemorySize, SMEM_BYTES);

    // gemm_tc_kernel is the 4th launch (ncu capture slot).
    xcvt_kernel<<<(N_NODES * IN_F / 2 + TB - 1) / TB, TB>>>(x);          // 1 (+csr zero)
    pack_kernel<<<(IN_F * 1024 + TB - 1) / TB, TB>>>(Wq0, Wk0, Wv0, Ws0,
                                                     bq0, bk0, bv0, bs0, IN_F);   // 2
    hist_kernel<<<(N_EDGES + TB - 1) / TB, TB>>>(dst);                   // 3
    gemm_tc_kernel<<<ggrid, 256, SMEM_BYTES>>>(xh, N_NODES, IN_F);       // 4 (profiled)
    scan1_kernel<<<SCAN_BLOCKS, 256>>>();                                // 5
    scan2_kernel<<<1, 256>>>();                                          // 6
    scan3_kernel<<<SCAN_BLOCKS, 256>>>();                                // 7 (+pool zero)
    scatter_kernel<<<(N_EDGES + TB - 1) / TB, TB>>>(src, dst);           // 8
    attn_kernel<<<attnBlocks, 256>>>();                                  // 9

    // layers 1..3 (HC -> HC)
    for (int l = 0; l < NLAYERS - 1; l++) {
        const float* wq = Wq + (size_t)l * HC * HC;
        const float* wk = Wk + (size_t)l * HC * HC;
        const float* wv = Wv + (size_t)l * HC * HC;
        const float* ws = Ws + (size_t)l * HC * HC;
        pack_kernel<<<(HC * 1024 + TB - 1) / TB, TB>>>(wq, wk, wv, ws,
                                                       bq + l * HC, bk + l * HC,
                                                       bv + l * HC, bs + l * HC, HC);
        gemm_tc_kernel<<<ggrid, 256, SMEM_BYTES>>>(hh, N_NODES, HC);
        attn_kernel<<<attnBlocks, 256>>>();
    }

    // pooling + fc
    pool_kernel<<<256, 256>>>(batch);
    fc_kernel<<<G_GRAPHS, OUT_F>>>(Wfc, bfc, out);
}

// round 16
// speedup vs baseline: 1.2115x; 1.0075x over previous
#include <cuda_runtime.h>
#include <cuda_fp16.h>
#include <math.h>

#define N_NODES 50000
#define N_EDGES 800000
#define IN_F    128
#define HC      256
#define G_GRAPHS 64
#define OUT_F   64
#define NLAYERS 4
#define SCAN_BLOCKS ((N_NODES + 255) / 256)   // 196

// ---------------- scratch (static device allocations; no cudaMalloc) ----------------
// NOTE: g_cnt is zero at module load; each call re-zeros it at the tail (pool_kernel),
// so every call (first run and every graph replay) starts with g_cnt == 0.
__device__ float  g_qs[(size_t)N_NODES * 512];    // [q|s] per node, fp32
__device__ __half g_kv[(size_t)N_NODES * 512];    // [k|v] per node, fp16
__device__ __half g_hh[(size_t)N_NODES * HC];     // layer activations, fp16
__device__ __half g_xh[(size_t)N_NODES * IN_F];   // input x converted to fp16
__device__ __half g_Wc[1024 * 256];               // packed W^T [1024 cols][K], fp16
__device__ float  g_bc[1024];
__device__ int    g_cnt[N_NODES];
__device__ int    g_off[N_NODES + 1];
__device__ int    g_btot[256];
__device__ int    g_epos[N_EDGES];                // per-edge slot within its dst segment
__device__ int    g_psrc[N_EDGES];
__device__ float  g_pool[G_GRAPHS * HC];
__device__ int    g_gcnt[G_GRAPHS];

// ---------------- x -> fp16 conversion + edge histogram (fused) ----------------
__global__ void xcvt_hist_kernel(const float* __restrict__ x, const int* __restrict__ dst) {
    int i = blockIdx.x * blockDim.x + threadIdx.x;
    int total = N_NODES * IN_F / 2;
    if (i < total) {
        float2 v = *(const float2*)(x + (size_t)i * 2);
        *(__half2*)(g_xh + (size_t)i * 2) = __floats2half2_rn(v.x, v.y);
    }
    if (i < N_EDGES) {
        int d = dst[i];
        g_epos[i] = atomicAdd(&g_cnt[d], 1);      // g_cnt pre-zeroed by previous call's tail
    }
}

// per-block exclusive scan + block totals
__global__ void scan1_kernel() {
    __shared__ int buf[256];
    int b = blockIdx.x, tid = threadIdx.x;
    int i = b * 256 + tid;
    int v = (i < N_NODES) ? g_cnt[i] : 0;
    buf[tid] = v;
    __syncthreads();
    #pragma unroll
    for (int ofs = 1; ofs < 256; ofs <<= 1) {
        int t = (tid >= ofs) ? buf[tid - ofs] : 0;
        __syncthreads();
        buf[tid] += t;
        __syncthreads();
    }
    if (i < N_NODES) g_off[i] = buf[tid] - v;
    if (tid == 255) g_btot[b] = buf[255];
}

// block-base computation (folded scan2) + add base + pool zero (fused)
__global__ void scan3_kernel() {
    __shared__ int buf[256];
    int b = blockIdx.x, tid = threadIdx.x;
    int v = (tid < b && tid < SCAN_BLOCKS) ? g_btot[tid] : 0;
    buf[tid] = v;
    __syncthreads();
    #pragma unroll
    for (int ofs = 128; ofs > 0; ofs >>= 1) {
        if (tid < ofs) buf[tid] += buf[tid + ofs];
        __syncthreads();
    }
    int base = buf[0];
    int i = b * 256 + tid;
    if (i < N_NODES) g_off[i] += base;
    if (i == 0) g_off[N_NODES] = N_EDGES;
    if (i < G_GRAPHS * HC) g_pool[i] = 0.f;
    if (i < G_GRAPHS) g_gcnt[i] = 0;
}

// atomic-free scatter using precomputed per-edge positions
__global__ void scatter_kernel(const int* __restrict__ src, const int* __restrict__ dst) {
    int e = blockIdx.x * blockDim.x + threadIdx.x;
    if (e < N_EDGES) {
        int d = dst[e];
        g_psrc[g_off[d] + g_epos[e]] = src[e];
    }
}

// ---------------- weight packing: [F,256]x4 -> W^T [1024][F], fp16 ----------------
__global__ void pack_kernel(const float* __restrict__ Wq, const float* __restrict__ Wk,
                            const float* __restrict__ Wv, const float* __restrict__ Ws,
                            const float* __restrict__ bq, const float* __restrict__ bk,
                            const float* __restrict__ bv, const float* __restrict__ bs,
                            int F) {
    int idx = blockIdx.x * blockDim.x + threadIdx.x;
    int total = F * 1024;
    if (idx < total) {
        int f   = idx & (F - 1);
        int col = idx / F;
        int sel = col >> 8;
        int c   = col & 255;
        const float* W = (sel == 0) ? Wq : (sel == 1) ? Wk : (sel == 2) ? Wv : Ws;
        g_Wc[idx] = __float2half_rn(W[f * 256 + c]);
    }
    if (idx < 1024) {
        int sel = idx >> 8, c = idx & 255;
        const float* b = (sel == 0) ? bq : (sel == 1) ? bk : (sel == 2) ? bv : bs;
        g_bc[idx] = b[c];
    }
}

// ---------------- fp16 tensor-core GEMM: 128x128 tile, GBK=64, 1 barrier/tile ----------------
#define GBM 128
#define GBN 128
#define GBK 64
#define HPITCH 72
#define ABUF (GBM * HPITCH)
#define BBUF (GBN * HPITCH)
#define SMEM_BYTES ((2 * ABUF + 2 * BBUF) * 2)   // 73728 bytes

__device__ __forceinline__ void cp_async16(void* smem_dst, const void* gsrc, int src_bytes) {
    unsigned sdst = (unsigned)__cvta_generic_to_shared(smem_dst);
    asm volatile("cp.async.ca.shared.global [%0], [%1], 16, %2;"
                 :: "r"(sdst), "l"(gsrc), "r"(src_bytes));
}
__device__ __forceinline__ void cp_async_commit() {
    asm volatile("cp.async.commit_group;");
}
template <int NN>
__device__ __forceinline__ void cp_async_wait() {
    asm volatile("cp.async.wait_group %0;" :: "n"(NN));
}

__device__ __forceinline__ void ldsm_x4(unsigned& r0, unsigned& r1, unsigned& r2, unsigned& r3,
                                        unsigned addr) {
    asm volatile("ldmatrix.sync.aligned.m8n8.x4.shared.b16 {%0,%1,%2,%3}, [%4];"
                 : "=r"(r0), "=r"(r1), "=r"(r2), "=r"(r3) : "r"(addr));
}
__device__ __forceinline__ void ldsm_x2(unsigned& r0, unsigned& r1, unsigned addr) {
    asm volatile("ldmatrix.sync.aligned.m8n8.x2.shared.b16 {%0,%1}, [%2];"
                 : "=r"(r0), "=r"(r1) : "r"(addr));
}

__device__ __forceinline__ void store_seg(int row, int col, float vx, float vy) {
    if (col < 256) {
        *(float2*)(g_qs + (size_t)row * 512 + col) = make_float2(vx, vy);
    } else if (col < 768) {
        *(__half2*)(g_kv + (size_t)row * 512 + (col - 256)) = __floats2half2_rn(vx, vy);
    } else {
        *(float2*)(g_qs + (size_t)row * 512 + 256 + (col - 768)) = make_float2(vx, vy);
    }
}

__global__ __launch_bounds__(256, 2) void gemm_tc_kernel(const __half* __restrict__ A, int M, int K) {
    extern __shared__ __half sm[];
    __half* AsBuf[2] = { sm, sm + ABUF };
    __half* BsBuf[2] = { sm + 2 * ABUF, sm + 2 * ABUF + BBUF };

    int tid  = threadIdx.x;
    int lane = tid & 31;
    int wid  = tid >> 5;
    int gid  = lane >> 2;
    int tig  = lane & 3;
    int warpM = wid & 1;
    int warpN = wid >> 1;

    int mBase = blockIdx.y * GBM;
    int nBase = blockIdx.x * GBN;

    int aRowOff = lane & 15;
    int aKOff   = (lane >> 4) << 3;
    int bColOff = lane & 7;
    int bKOff   = ((lane >> 3) & 1) << 3;
    unsigned aOff[4], bOff[4];
    #pragma unroll
    for (int mt = 0; mt < 4; mt++)
        aOff[mt] = ((warpM * 64 + mt * 16 + aRowOff) * HPITCH + aKOff) * 2;
    #pragma unroll
    for (int nt = 0; nt < 4; nt++)
        bOff[nt] = ((warpN * 32 + nt * 8 + bColOff) * HPITCH + bKOff) * 2;
    unsigned asbB[2] = { (unsigned)__cvta_generic_to_shared(AsBuf[0]),
                         (unsigned)__cvta_generic_to_shared(AsBuf[1]) };
    unsigned bsbB[2] = { (unsigned)__cvta_generic_to_shared(BsBuf[0]),
                         (unsigned)__cvta_generic_to_shared(BsBuf[1]) };

    float c[4][4][4];
    #pragma unroll
    for (int i = 0; i < 4; i++)
        #pragma unroll
        for (int j = 0; j < 4; j++)
            #pragma unroll
            for (int r = 0; r < 4; r++) c[i][j][r] = 0.f;

    int nTiles = K / GBK;

    auto load_tile = [&](int bufIdx, int k0) {
        __half* As = AsBuf[bufIdx];
        __half* Bs = BsBuf[bufIdx];
        #pragma unroll
        for (int t = 0; t < 4; t++) {
            int idx = tid + t * 256;
            int row = idx >> 3;
            int ck  = idx & 7;
            int gm  = mBase + row;
            int ok  = (gm < M) ? 16 : 0;
            const __half* srcA = A + (size_t)((gm < M) ? gm : 0) * K + k0 + ck * 8;
            cp_async16(&As[row * HPITCH + ck * 8], srcA, ok);
            const __half* srcB = g_Wc + (size_t)(nBase + row) * K + k0 + ck * 8;
            cp_async16(&Bs[row * HPITCH + ck * 8], srcB, 16);
        }
        cp_async_commit();
    };

    load_tile(0, 0);

    unsigned af[2][4][4];
    unsigned bf[2][4][2];

    for (int kt = 0; kt < nTiles; kt++) {
        int buf = kt & 1;
        cp_async_wait<0>();
        __syncthreads();
        if (kt + 1 < nTiles) load_tile(buf ^ 1, (kt + 1) * GBK);

        unsigned asb = asbB[buf];
        unsigned bsb = bsbB[buf];

        auto load_frags = [&](int s, int kk) {
            unsigned kByte = (unsigned)(kk * 2);
            #pragma unroll
            for (int mt = 0; mt < 4; mt++)
                ldsm_x4(af[s][mt][0], af[s][mt][1], af[s][mt][2], af[s][mt][3],
                        asb + aOff[mt] + kByte);
            #pragma unroll
            for (int nt = 0; nt < 4; nt++)
                ldsm_x2(bf[s][nt][0], bf[s][nt][1], bsb + bOff[nt] + kByte);
        };

        load_frags(0, 0);
        #pragma unroll
        for (int ks = 0; ks < 4; ks++) {
            int cur = ks & 1;
            if (ks < 3) load_frags(cur ^ 1, (ks + 1) * 16);
            #pragma unroll
            for (int mt = 0; mt < 4; mt++)
                #pragma unroll
                for (int nt = 0; nt < 4; nt++) {
                    asm volatile(
                        "mma.sync.aligned.m16n8k16.row.col.f32.f16.f16.f32 "
                        "{%0,%1,%2,%3}, {%4,%5,%6,%7}, {%8,%9}, {%0,%1,%2,%3};"
                        : "+f"(c[mt][nt][0]), "+f"(c[mt][nt][1]),
                          "+f"(c[mt][nt][2]), "+f"(c[mt][nt][3])
                        : "r"(af[cur][mt][0]), "r"(af[cur][mt][1]),
                          "r"(af[cur][mt][2]), "r"(af[cur][mt][3]),
                          "r"(bf[cur][nt][0]), "r"(bf[cur][nt][1]));
                }
        }
    }

    #pragma unroll
    for (int nt = 0; nt < 4; nt++) {
        int col = nBase + warpN * 32 + nt * 8 + tig * 2;
        float2 bias = *(const float2*)(g_bc + col);
        #pragma unroll
        for (int mt = 0; mt < 4; mt++) {
            int row0 = mBase + warpM * 64 + mt * 16 + gid;
            if (row0 < M)
                store_seg(row0, col, c[mt][nt][0] + bias.x, c[mt][nt][1] + bias.y);
            int row1 = row0 + 8;
            if (row1 < M)
                store_seg(row1, col, c[mt][nt][2] + bias.x, c[mt][nt][3] + bias.y);
        }
    }
}

// ---------------- attention: one warp per dst node, depth-2 index prefetch ----------------
__global__ __launch_bounds__(256) void attn_kernel() {
    int warp = (blockIdx.x * blockDim.x + threadIdx.x) >> 5;
    int lane = threadIdx.x & 31;
    if (warp >= N_NODES) return;

    const float* base_q = g_qs + (size_t)warp * 512 + lane * 8;
    float4 q0 = *(const float4*)(base_q);
    float4 q1 = *(const float4*)(base_q + 4);

    float m = -INFINITY, s = 0.f;
    float4 a0 = make_float4(0.f, 0.f, 0.f, 0.f);
    float4 a1 = make_float4(0.f, 0.f, 0.f, 0.f);

    int e0 = g_off[warp], e1 = g_off[warp + 1];

    uint4 kc = make_uint4(0, 0, 0, 0), vc = make_uint4(0, 0, 0, 0);
    int sB = 0;
    if (e0 < e1) {
        const __half* kvb = g_kv + (size_t)g_psrc[e0] * 512 + lane * 8;
        kc = *(const uint4*)(kvb);
        vc = *(const uint4*)(kvb + 256);
        if (e0 + 1 < e1) sB = g_psrc[e0 + 1];
    }

    for (int i = e0; i < e1; i++) {
        uint4 kcur = kc, vcur = vc;
        int sC = (i + 2 < e1) ? g_psrc[i + 2] : 0;
        if (i + 1 < e1) {
            const __half* kvb = g_kv + (size_t)sB * 512 + lane * 8;
            kc = *(const uint4*)(kvb);
            vc = *(const uint4*)(kvb + 256);
        }
        sB = sC;

        float2 k01 = __half22float2(*(const __half2*)&kcur.x);
        float2 k23 = __half22float2(*(const __half2*)&kcur.y);
        float2 k45 = __half22float2(*(const __half2*)&kcur.z);
        float2 k67 = __half22float2(*(const __half2*)&kcur.w);

        float d = q0.x * k01.x + q0.y * k01.y + q0.z * k23.x + q0.w * k23.y
                + q1.x * k45.x + q1.y * k45.y + q1.z * k67.x + q1.w * k67.y;
        d += __shfl_xor_sync(0xFFFFFFFFu, d, 1);
        d += __shfl_xor_sync(0xFFFFFFFFu, d, 2);
        float logit = d * 0.17677669529663687f;   // 1/sqrt(32)

        float mN = fmaxf(m, logit);
        float sc = __expf(m - mN);
        float p  = __expf(logit - mN);
        m = mN;
        s = s * sc + p;

        float2 v01 = __half22float2(*(const __half2*)&vcur.x);
        float2 v23 = __half22float2(*(const __half2*)&vcur.y);
        float2 v45 = __half22float2(*(const __half2*)&vcur.z);
        float2 v67 = __half22float2(*(const __half2*)&vcur.w);

        a0.x = a0.x * sc + p * v01.x; a0.y = a0.y * sc + p * v01.y;
        a0.z = a0.z * sc + p * v23.x; a0.w = a0.w * sc + p * v23.y;
        a1.x = a1.x * sc + p * v45.x; a1.y = a1.y * sc + p * v45.y;
        a1.z = a1.z * sc + p * v67.x; a1.w = a1.w * sc + p * v67.y;
    }

    float inv = 1.f / (s + 1e-16f);
    const float* sb = g_qs + (size_t)warp * 512 + 256 + lane * 8;
    float4 s0 = *(const float4*)(sb);
    float4 s1 = *(const float4*)(sb + 4);
    float r0 = fmaxf(a0.x * inv + s0.x, 0.f);
    float r1 = fmaxf(a0.y * inv + s0.y, 0.f);
    float r2 = fmaxf(a0.z * inv + s0.z, 0.f);
    float r3 = fmaxf(a0.w * inv + s0.w, 0.f);
    float r4 = fmaxf(a1.x * inv + s1.x, 0.f);
    float r5 = fmaxf(a1.y * inv + s1.y, 0.f);
    float r6 = fmaxf(a1.z * inv + s1.z, 0.f);
    float r7 = fmaxf(a1.w * inv + s1.w, 0.f);

    __half* hb = g_hh + (size_t)warp * 256 + lane * 8;
    uint4 packed;
    *(__half2*)&packed.x = __floats2half2_rn(r0, r1);
    *(__half2*)&packed.y = __floats2half2_rn(r2, r3);
    *(__half2*)&packed.z = __floats2half2_rn(r4, r5);
    *(__half2*)&packed.w = __floats2half2_rn(r6, r7);
    *(uint4*)hb = packed;
}

// ---------------- pooling (+ g_cnt re-zero for next replay) ----------------
__global__ __launch_bounds__(256) void pool_kernel(const int* __restrict__ batch) {
    // re-zero edge histogram for the next call/replay (g_cnt fully consumed by now)
    int gidx = blockIdx.x * blockDim.x + threadIdx.x;
    if (gidx < N_NODES) g_cnt[gidx] = 0;

    int c = threadIdx.x;
    int per = (N_NODES + gridDim.x - 1) / gridDim.x;
    int start = blockIdx.x * per;
    int end = min(N_NODES, start + per);
    if (start >= end) return;
    int cur = batch[start];
    float acc = 0.f;
    int cnt = 0;
    for (int i = start; i < end; i++) {
        int b = batch[i];
        if (b != cur) {
            atomicAdd(&g_pool[cur * HC + c], acc);
            if (c == 0) atomicAdd(&g_gcnt[cur], cnt);
            acc = 0.f; cnt = 0; cur = b;
        }
        acc += __half2float(g_hh[(size_t)i * HC + c]);
        cnt++;
    }
    atomicAdd(&g_pool[cur * HC + c], acc);
    if (c == 0) atomicAdd(&g_gcnt[cur], cnt);
}

__global__ void fc_kernel(const float* __restrict__ Wfc, const float* __restrict__ bfc,
                          float* __restrict__ out) {
    int g = blockIdx.x;
    int o = threadIdx.x;
    __shared__ float p[HC];
    float inv = 1.f / fmaxf((float)g_gcnt[g], 1.f);
    for (int i = o; i < HC; i += OUT_F) p[i] = g_pool[g * HC + i] * inv;
    __syncthreads();
    float acc = bfc[o];
    #pragma unroll 8
    for (int f = 0; f < HC; f++) acc += p[f] * Wfc[f * OUT_F + o];
    out[g * OUT_F + o] = acc;
}

// ---------------- launch ----------------
extern "C" void kernel_launch(void* const* d_in, const int* in_sizes, int n_in,
                              void* d_out, int out_size) {
    const float* x    = (const float*)d_in[0];
    const int*   ei   = (const int*)d_in[1];
    const int*   src  = ei;
    const int*   dst  = ei + N_EDGES;
    const int*   batch = (const int*)d_in[2];
    const float* Wq0 = (const float*)d_in[3];
    const float* bq0 = (const float*)d_in[4];
    const float* Wk0 = (const float*)d_in[5];
    const float* bk0 = (const float*)d_in[6];
    const float* Wv0 = (const float*)d_in[7];
    const float* bv0 = (const float*)d_in[8];
    const float* Ws0 = (const float*)d_in[9];
    const float* bs0 = (const float*)d_in[10];
    const float* Wq  = (const float*)d_in[11];
    const float* bq  = (const float*)d_in[12];
    const float* Wk  = (const float*)d_in[13];
    const float* bk  = (const float*)d_in[14];
    const float* Wv  = (const float*)d_in[15];
    const float* bv  = (const float*)d_in[16];
    const float* Ws  = (const float*)d_in[17];
    const float* bs  = (const float*)d_in[18];
    const float* Wfc = (const float*)d_in[19];
    const float* bfc = (const float*)d_in[20];
    float* out = (float*)d_out;

    const int TB = 256;
    dim3 ggrid(1024 / GBN, (N_NODES + GBM - 1) / GBM);   // (8, 391)
    int attnBlocks = (N_NODES + 7) / 8;

    __half* xh = nullptr;
    __half* hh = nullptr;
    cudaGetSymbolAddress((void**)&xh, g_xh);
    cudaGetSymbolAddress((void**)&hh, g_hh);

    cudaFuncSetAttribute(gemm_tc_kernel, cudaFuncAttributeMaxDynamicSharedMemorySize, SMEM_BYTES);

    // gemm_tc_kernel stays the 4th launch (ncu capture slot).
    xcvt_hist_kernel<<<(N_NODES * IN_F / 2 + TB - 1) / TB, TB>>>(x, dst);          // 1
    pack_kernel<<<(IN_F * 1024 + TB - 1) / TB, TB>>>(Wq0, Wk0, Wv0, Ws0,
                                                     bq0, bk0, bv0, bs0, IN_F);    // 2
    scan1_kernel<<<SCAN_BLOCKS, 256>>>();                                          // 3
    gemm_tc_kernel<<<ggrid, 256, SMEM_BYTES>>>(xh, N_NODES, IN_F);                 // 4 (profiled)
    scan3_kernel<<<SCAN_BLOCKS, 256>>>();                                          // 5 (+pool zero)
    scatter_kernel<<<(N_EDGES + TB - 1) / TB, TB>>>(src, dst);                     // 6
    attn_kernel<<<attnBlocks, 256>>>();                                            // 7

    // layers 1..3 (HC -> HC)
    for (int l = 0; l < NLAYERS - 1; l++) {
        const float* wq = Wq + (size_t)l * HC * HC;
        const float* wk = Wk + (size_t)l * HC * HC;
        const float* wv = Wv + (size_t)l * HC * HC;
        const float* ws = Ws + (size_t)l * HC * HC;
        pack_kernel<<<(HC * 1024 + TB - 1) / TB, TB>>>(wq, wk, wv, ws,
                                                       bq + l * HC, bk + l * HC,
                                                       bv + l * HC, bs + l * HC, HC);
        gemm_tc_kernel<<<ggrid, 256, SMEM_BYTES>>>(hh, N_NODES, HC);
        attn_kernel<<<attnBlocks, 256>>>();
    }

    // pooling (+ g_cnt re-zero) + fc
    pool_kernel<<<256, 256>>>(batch);
    fc_kernel<<<G_GRAPHS, OUT_F>>>(Wfc, bfc, out);
}

// round 17
// speedup vs baseline: 1.2518x; 1.0333x over previous
#include <cuda_runtime.h>
#include <cuda_fp16.h>
#include <math.h>

#define N_NODES 50000
#define N_EDGES 800000
#define IN_F    128
#define HC      256
#define G_GRAPHS 64
#define OUT_F   64
#define NLAYERS 4
#define SCAN_BLOCKS ((N_NODES + 255) / 256)   // 196

// weight slab layout: layer0 [1024][128] at 0; layers 1..3 [1024][256] after
#define W0_SIZE   (1024 * IN_F)               // 131072
#define WL_SIZE   (1024 * HC)                 // 262144
#define WC_TOTAL  (W0_SIZE + 3 * WL_SIZE)     // 917504 halfs

// ---------------- scratch (static device allocations; no cudaMalloc) ----------------
// NOTE: g_cnt is zero at module load; each call re-zeros it at the tail (pool_kernel),
// so every call (first run and every graph replay) starts with g_cnt == 0.
__device__ float  g_qs[(size_t)N_NODES * 512];    // [q|s] per node, fp32
__device__ __half g_kv[(size_t)N_NODES * 512];    // [k|v] per node, fp16
__device__ __half g_hh[(size_t)N_NODES * HC];     // layer activations, fp16
__device__ __half g_xh[(size_t)N_NODES * IN_F];   // input x converted to fp16
__device__ __half g_Wc[WC_TOTAL];                 // packed W^T, all 4 layers, fp16
__device__ float  g_bc[4 * 1024];                 // packed biases, all 4 layers
__device__ int    g_cnt[N_NODES];
__device__ int    g_off[N_NODES + 1];
__device__ int    g_btot[256];
__device__ int    g_epos[N_EDGES];                // per-edge slot within its dst segment
__device__ int    g_psrc[N_EDGES];
__device__ float  g_pool[G_GRAPHS * HC];
__device__ int    g_gcnt[G_GRAPHS];

// ---------------- prep: xcvt + hist + pack all weights/biases (one launch) ----------------
__global__ void prep_kernel(const float* __restrict__ x, const int* __restrict__ dst,
                            const float* __restrict__ Wq0, const float* __restrict__ Wk0,
                            const float* __restrict__ Wv0, const float* __restrict__ Ws0,
                            const float* __restrict__ Wq,  const float* __restrict__ Wk,
                            const float* __restrict__ Wv,  const float* __restrict__ Ws,
                            const float* __restrict__ bq0, const float* __restrict__ bk0,
                            const float* __restrict__ bv0, const float* __restrict__ bs0,
                            const float* __restrict__ bq,  const float* __restrict__ bk,
                            const float* __restrict__ bv,  const float* __restrict__ bs) {
    int i = blockIdx.x * blockDim.x + threadIdx.x;

    // x -> fp16 (1.6M threads)
    if (i < N_NODES * IN_F / 2) {
        float2 v = *(const float2*)(x + (size_t)i * 2);
        *(__half2*)(g_xh + (size_t)i * 2) = __floats2half2_rn(v.x, v.y);
    }
    // edge histogram (800K threads)
    if (i < N_EDGES) {
        g_epos[i] = atomicAdd(&g_cnt[dst[i]], 1);   // g_cnt pre-zeroed by previous call's tail
    }
    // weight packing (917504 threads)
    if (i < WC_TOTAL) {
        if (i < W0_SIZE) {
            int f   = i & (IN_F - 1);
            int col = i >> 7;
            int sel = col >> 8, c = col & 255;
            const float* W = (sel == 0) ? Wq0 : (sel == 1) ? Wk0 : (sel == 2) ? Wv0 : Ws0;
            g_Wc[i] = __float2half_rn(W[f * 256 + c]);
        } else {
            int idx2 = i - W0_SIZE;
            int l    = idx2 >> 18;              // 0..2
            int r    = idx2 & (WL_SIZE - 1);
            int f    = r & (HC - 1);
            int col  = r >> 8;
            int sel  = col >> 8, c = col & 255;
            const float* W = (sel == 0) ? Wq : (sel == 1) ? Wk : (sel == 2) ? Wv : Ws;
            g_Wc[i] = __float2half_rn(W[((size_t)l * HC + f) * 256 + c]);
        }
    }
    // bias packing (4096 threads)
    if (i < 4 * 1024) {
        int l = i >> 10;
        int j = i & 1023;
        int sel = j >> 8, c = j & 255;
        float v;
        if (l == 0) {
            const float* b = (sel == 0) ? bq0 : (sel == 1) ? bk0 : (sel == 2) ? bv0 : bs0;
            v = b[c];
        } else {
            const float* b = (sel == 0) ? bq : (sel == 1) ? bk : (sel == 2) ? bv : bs;
            v = b[(l - 1) * HC + c];
        }
        g_bc[i] = v;
    }
}

// per-block exclusive scan + block totals
__global__ void scan1_kernel() {
    __shared__ int buf[256];
    int b = blockIdx.x, tid = threadIdx.x;
    int i = b * 256 + tid;
    int v = (i < N_NODES) ? g_cnt[i] : 0;
    buf[tid] = v;
    __syncthreads();
    #pragma unroll
    for (int ofs = 1; ofs < 256; ofs <<= 1) {
        int t = (tid >= ofs) ? buf[tid - ofs] : 0;
        __syncthreads();
        buf[tid] += t;
        __syncthreads();
    }
    if (i < N_NODES) g_off[i] = buf[tid] - v;
    if (tid == 255) g_btot[b] = buf[255];
}

// block-base (folded scan2) + add base + pool zero
__global__ void scan3_kernel() {
    __shared__ int buf[256];
    int b = blockIdx.x, tid = threadIdx.x;
    int v = (tid < b && tid < SCAN_BLOCKS) ? g_btot[tid] : 0;
    buf[tid] = v;
    __syncthreads();
    #pragma unroll
    for (int ofs = 128; ofs > 0; ofs >>= 1) {
        if (tid < ofs) buf[tid] += buf[tid + ofs];
        __syncthreads();
    }
    int base = buf[0];
    int i = b * 256 + tid;
    if (i < N_NODES) g_off[i] += base;
    if (i == 0) g_off[N_NODES] = N_EDGES;
    if (i < G_GRAPHS * HC) g_pool[i] = 0.f;
    if (i < G_GRAPHS) g_gcnt[i] = 0;
}

// atomic-free scatter
__global__ void scatter_kernel(const int* __restrict__ src, const int* __restrict__ dst) {
    int e = blockIdx.x * blockDim.x + threadIdx.x;
    if (e < N_EDGES) {
        g_psrc[g_off[dst[e]] + g_epos[e]] = src[e];
    }
}

// ---------------- fp16 tensor-core GEMM: 128x128 tile, GBK=64, 1 barrier/tile ----------------
#define GBM 128
#define GBN 128
#define GBK 64
#define HPITCH 72
#define ABUF (GBM * HPITCH)
#define BBUF (GBN * HPITCH)
#define SMEM_BYTES ((2 * ABUF + 2 * BBUF) * 2)   // 73728 bytes

__device__ __forceinline__ void cp_async16(void* smem_dst, const void* gsrc, int src_bytes) {
    unsigned sdst = (unsigned)__cvta_generic_to_shared(smem_dst);
    asm volatile("cp.async.ca.shared.global [%0], [%1], 16, %2;"
                 :: "r"(sdst), "l"(gsrc), "r"(src_bytes));
}
__device__ __forceinline__ void cp_async_commit() {
    asm volatile("cp.async.commit_group;");
}
template <int NN>
__device__ __forceinline__ void cp_async_wait() {
    asm volatile("cp.async.wait_group %0;" :: "n"(NN));
}

__device__ __forceinline__ void ldsm_x4(unsigned& r0, unsigned& r1, unsigned& r2, unsigned& r3,
                                        unsigned addr) {
    asm volatile("ldmatrix.sync.aligned.m8n8.x4.shared.b16 {%0,%1,%2,%3}, [%4];"
                 : "=r"(r0), "=r"(r1), "=r"(r2), "=r"(r3) : "r"(addr));
}

__device__ __forceinline__ void store_seg(int row, int col, float vx, float vy) {
    if (col < 256) {
        *(float2*)(g_qs + (size_t)row * 512 + col) = make_float2(vx, vy);
    } else if (col < 768) {
        *(__half2*)(g_kv + (size_t)row * 512 + (col - 256)) = __floats2half2_rn(vx, vy);
    } else {
        *(float2*)(g_qs + (size_t)row * 512 + 256 + (col - 768)) = make_float2(vx, vy);
    }
}

__global__ __launch_bounds__(256, 2) void gemm_tc_kernel(const __half* __restrict__ A,
                                                         const __half* __restrict__ W,
                                                         const float* __restrict__ bc,
                                                         int M, int K) {
    extern __shared__ __half sm[];
    __half* AsBuf[2] = { sm, sm + ABUF };
    __half* BsBuf[2] = { sm + 2 * ABUF, sm + 2 * ABUF + BBUF };

    int tid  = threadIdx.x;
    int lane = tid & 31;
    int wid  = tid >> 5;
    int gid  = lane >> 2;
    int tig  = lane & 3;
    int warpM = wid & 1;
    int warpN = wid >> 1;

    int mBase = blockIdx.y * GBM;
    int nBase = blockIdx.x * GBN;

    // A fragment offsets (x4 per m-tile)
    int aRowOff = lane & 15;
    int aKOff   = (lane >> 4) << 3;
    // B fragment offsets: paired x4 over two adjacent 8-col n-tiles (R12-verified mapping)
    int bColOff = ((lane >> 4) << 3) + (lane & 7);   // matrices 0,1 -> +0..7 ; 2,3 -> +8..15
    int bKOff   = ((lane >> 3) & 1) << 3;            // matrices 0,2 -> k+0 ; 1,3 -> k+8

    unsigned aOff[4], bOff[2];
    #pragma unroll
    for (int mt = 0; mt < 4; mt++)
        aOff[mt] = ((warpM * 64 + mt * 16 + aRowOff) * HPITCH + aKOff) * 2;
    #pragma unroll
    for (int j = 0; j < 2; j++)
        bOff[j] = ((warpN * 32 + j * 16 + bColOff) * HPITCH + bKOff) * 2;
    unsigned asbB[2] = { (unsigned)__cvta_generic_to_shared(AsBuf[0]),
                         (unsigned)__cvta_generic_to_shared(AsBuf[1]) };
    unsigned bsbB[2] = { (unsigned)__cvta_generic_to_shared(BsBuf[0]),
                         (unsigned)__cvta_generic_to_shared(BsBuf[1]) };

    float c[4][4][4];
    #pragma unroll
    for (int i = 0; i < 4; i++)
        #pragma unroll
        for (int j = 0; j < 4; j++)
            #pragma unroll
            for (int r = 0; r < 4; r++) c[i][j][r] = 0.f;

    int nTiles = K / GBK;

    auto load_tile = [&](int bufIdx, int k0) {
        __half* As = AsBuf[bufIdx];
        __half* Bs = BsBuf[bufIdx];
        #pragma unroll
        for (int t = 0; t < 4; t++) {
            int idx = tid + t * 256;
            int row = idx >> 3;
            int ck  = idx & 7;
            int gm  = mBase + row;
            int ok  = (gm < M) ? 16 : 0;
            const __half* srcA = A + (size_t)((gm < M) ? gm : 0) * K + k0 + ck * 8;
            cp_async16(&As[row * HPITCH + ck * 8], srcA, ok);
            const __half* srcB = W + (size_t)(nBase + row) * K + k0 + ck * 8;
            cp_async16(&Bs[row * HPITCH + ck * 8], srcB, 16);
        }
        cp_async_commit();
    };

    load_tile(0, 0);

    unsigned af[2][4][4];
    unsigned bf[2][4][2];

    for (int kt = 0; kt < nTiles; kt++) {
        int buf = kt & 1;
        cp_async_wait<0>();
        __syncthreads();
        if (kt + 1 < nTiles) load_tile(buf ^ 1, (kt + 1) * GBK);

        unsigned asb = asbB[buf];
        unsigned bsb = bsbB[buf];

        auto load_frags = [&](int s, int kk) {
            unsigned kByte = (unsigned)(kk * 2);
            #pragma unroll
            for (int mt = 0; mt < 4; mt++)
                ldsm_x4(af[s][mt][0], af[s][mt][1], af[s][mt][2], af[s][mt][3],
                        asb + aOff[mt] + kByte);
            #pragma unroll
            for (int j = 0; j < 2; j++)
                ldsm_x4(bf[s][2 * j][0], bf[s][2 * j][1],
                        bf[s][2 * j + 1][0], bf[s][2 * j + 1][1],
                        bsb + bOff[j] + kByte);
        };

        load_frags(0, 0);
        #pragma unroll
        for (int ks = 0; ks < 4; ks++) {
            int cur = ks & 1;
            if (ks < 3) load_frags(cur ^ 1, (ks + 1) * 16);
            #pragma unroll
            for (int mt = 0; mt < 4; mt++)
                #pragma unroll
                for (int nt = 0; nt < 4; nt++) {
                    asm volatile(
                        "mma.sync.aligned.m16n8k16.row.col.f32.f16.f16.f32 "
                        "{%0,%1,%2,%3}, {%4,%5,%6,%7}, {%8,%9}, {%0,%1,%2,%3};"
                        : "+f"(c[mt][nt][0]), "+f"(c[mt][nt][1]),
                          "+f"(c[mt][nt][2]), "+f"(c[mt][nt][3])
                        : "r"(af[cur][mt][0]), "r"(af[cur][mt][1]),
                          "r"(af[cur][mt][2]), "r"(af[cur][mt][3]),
                          "r"(bf[cur][nt][0]), "r"(bf[cur][nt][1]));
                }
        }
    }

    #pragma unroll
    for (int nt = 0; nt < 4; nt++) {
        int col = nBase + warpN * 32 + nt * 8 + tig * 2;
        float2 bias = *(const float2*)(bc + col);
        #pragma unroll
        for (int mt = 0; mt < 4; mt++) {
            int row0 = mBase + warpM * 64 + mt * 16 + gid;
            if (row0 < M)
                store_seg(row0, col, c[mt][nt][0] + bias.x, c[mt][nt][1] + bias.y);
            int row1 = row0 + 8;
            if (row1 < M)
                store_seg(row1, col, c[mt][nt][2] + bias.x, c[mt][nt][3] + bias.y);
        }
    }
}

// ---------------- attention: one warp per dst node, depth-2 index prefetch ----------------
__global__ __launch_bounds__(256) void attn_kernel() {
    int warp = (blockIdx.x * blockDim.x + threadIdx.x) >> 5;
    int lane = threadIdx.x & 31;
    if (warp >= N_NODES) return;

    const float* base_q = g_qs + (size_t)warp * 512 + lane * 8;
    float4 q0 = *(const float4*)(base_q);
    float4 q1 = *(const float4*)(base_q + 4);

    float m = -INFINITY, s = 0.f;
    float4 a0 = make_float4(0.f, 0.f, 0.f, 0.f);
    float4 a1 = make_float4(0.f, 0.f, 0.f, 0.f);

    int e0 = g_off[warp], e1 = g_off[warp + 1];

    uint4 kc = make_uint4(0, 0, 0, 0), vc = make_uint4(0, 0, 0, 0);
    int sB = 0;
    if (e0 < e1) {
        const __half* kvb = g_kv + (size_t)g_psrc[e0] * 512 + lane * 8;
        kc = *(const uint4*)(kvb);
        vc = *(const uint4*)(kvb + 256);
        if (e0 + 1 < e1) sB = g_psrc[e0 + 1];
    }

    for (int i = e0; i < e1; i++) {
        uint4 kcur = kc, vcur = vc;
        int sC = (i + 2 < e1) ? g_psrc[i + 2] : 0;
        if (i + 1 < e1) {
            const __half* kvb = g_kv + (size_t)sB * 512 + lane * 8;
            kc = *(const uint4*)(kvb);
            vc = *(const uint4*)(kvb + 256);
        }
        sB = sC;

        float2 k01 = __half22float2(*(const __half2*)&kcur.x);
        float2 k23 = __half22float2(*(const __half2*)&kcur.y);
        float2 k45 = __half22float2(*(const __half2*)&kcur.z);
        float2 k67 = __half22float2(*(const __half2*)&kcur.w);

        float d = q0.x * k01.x + q0.y * k01.y + q0.z * k23.x + q0.w * k23.y
                + q1.x * k45.x + q1.y * k45.y + q1.z * k67.x + q1.w * k67.y;
        d += __shfl_xor_sync(0xFFFFFFFFu, d, 1);
        d += __shfl_xor_sync(0xFFFFFFFFu, d, 2);
        float logit = d * 0.17677669529663687f;   // 1/sqrt(32)

        float mN = fmaxf(m, logit);
        float sc = __expf(m - mN);
        float p  = __expf(logit - mN);
        m = mN;
        s = s * sc + p;

        float2 v01 = __half22float2(*(const __half2*)&vcur.x);
        float2 v23 = __half22float2(*(const __half2*)&vcur.y);
        float2 v45 = __half22float2(*(const __half2*)&vcur.z);
        float2 v67 = __half22float2(*(const __half2*)&vcur.w);

        a0.x = a0.x * sc + p * v01.x; a0.y = a0.y * sc + p * v01.y;
        a0.z = a0.z * sc + p * v23.x; a0.w = a0.w * sc + p * v23.y;
        a1.x = a1.x * sc + p * v45.x; a1.y = a1.y * sc + p * v45.y;
        a1.z = a1.z * sc + p * v67.x; a1.w = a1.w * sc + p * v67.y;
    }

    float inv = 1.f / (s + 1e-16f);
    const float* sb = g_qs + (size_t)warp * 512 + 256 + lane * 8;
    float4 s0 = *(const float4*)(sb);
    float4 s1 = *(const float4*)(sb + 4);
    float r0 = fmaxf(a0.x * inv + s0.x, 0.f);
    float r1 = fmaxf(a0.y * inv + s0.y, 0.f);
    float r2 = fmaxf(a0.z * inv + s0.z, 0.f);
    float r3 = fmaxf(a0.w * inv + s0.w, 0.f);
    float r4 = fmaxf(a1.x * inv + s1.x, 0.f);
    float r5 = fmaxf(a1.y * inv + s1.y, 0.f);
    float r6 = fmaxf(a1.z * inv + s1.z, 0.f);
    float r7 = fmaxf(a1.w * inv + s1.w, 0.f);

    __half* hb = g_hh + (size_t)warp * 256 + lane * 8;
    uint4 packed;
    *(__half2*)&packed.x = __floats2half2_rn(r0, r1);
    *(__half2*)&packed.y = __floats2half2_rn(r2, r3);
    *(__half2*)&packed.z = __floats2half2_rn(r4, r5);
    *(__half2*)&packed.w = __floats2half2_rn(r6, r7);
    *(uint4*)hb = packed;
}

// ---------------- pooling (+ g_cnt re-zero for next replay) ----------------
__global__ __launch_bounds__(256) void pool_kernel(const int* __restrict__ batch) {
    int gidx = blockIdx.x * blockDim.x + threadIdx.x;
    if (gidx < N_NODES) g_cnt[gidx] = 0;

    int c = threadIdx.x;
    int per = (N_NODES + gridDim.x - 1) / gridDim.x;
    int start = blockIdx.x * per;
    int end = min(N_NODES, start + per);
    if (start >= end) return;
    int cur = batch[start];
    float acc = 0.f;
    int cnt = 0;
    for (int i = start; i < end; i++) {
        int b = batch[i];
        if (b != cur) {
            atomicAdd(&g_pool[cur * HC + c], acc);
            if (c == 0) atomicAdd(&g_gcnt[cur], cnt);
            acc = 0.f; cnt = 0; cur = b;
        }
        acc += __half2float(g_hh[(size_t)i * HC + c]);
        cnt++;
    }
    atomicAdd(&g_pool[cur * HC + c], acc);
    if (c == 0) atomicAdd(&g_gcnt[cur], cnt);
}

__global__ void fc_kernel(const float* __restrict__ Wfc, const float* __restrict__ bfc,
                          float* __restrict__ out) {
    int g = blockIdx.x;
    int o = threadIdx.x;
    __shared__ float p[HC];
    float inv = 1.f / fmaxf((float)g_gcnt[g], 1.f);
    for (int i = o; i < HC; i += OUT_F) p[i] = g_pool[g * HC + i] * inv;
    __syncthreads();
    float acc = bfc[o];
    #pragma unroll 8
    for (int f = 0; f < HC; f++) acc += p[f] * Wfc[f * OUT_F + o];
    out[g * OUT_F + o] = acc;
}

// ---------------- launch ----------------
extern "C" void kernel_launch(void* const* d_in, const int* in_sizes, int n_in,
                              void* d_out, int out_size) {
    const float* x    = (const float*)d_in[0];
    const int*   ei   = (const int*)d_in[1];
    const int*   src  = ei;
    const int*   dst  = ei + N_EDGES;
    const int*   batch = (const int*)d_in[2];
    const float* Wq0 = (const float*)d_in[3];
    const float* bq0 = (const float*)d_in[4];
    const float* Wk0 = (const float*)d_in[5];
    const float* bk0 = (const float*)d_in[6];
    const float* Wv0 = (const float*)d_in[7];
    const float* bv0 = (const float*)d_in[8];
    const float* Ws0 = (const float*)d_in[9];
    const float* bs0 = (const float*)d_in[10];
    const float* Wq  = (const float*)d_in[11];
    const float* bq  = (const float*)d_in[12];
    const float* Wk  = (const float*)d_in[13];
    const float* bk  = (const float*)d_in[14];
    const float* Wv  = (const float*)d_in[15];
    const float* bv  = (const float*)d_in[16];
    const float* Ws  = (const float*)d_in[17];
    const float* bs  = (const float*)d_in[18];
    const float* Wfc = (const float*)d_in[19];
    const float* bfc = (const float*)d_in[20];
    float* out = (float*)d_out;

    const int TB = 256;
    dim3 ggrid(1024 / GBN, (N_NODES + GBM - 1) / GBM);   // (8, 391)
    int attnBlocks = (N_NODES + 7) / 8;
    int prepBlocks = (N_NODES * IN_F / 2 + TB - 1) / TB;  // covers all prep roles

    __half* xh = nullptr;
    __half* hh = nullptr;
    __half* wc = nullptr;
    float*  bc = nullptr;
    cudaGetSymbolAddress((void**)&xh, g_xh);
    cudaGetSymbolAddress((void**)&hh, g_hh);
    cudaGetSymbolAddress((void**)&wc, g_Wc);
    cudaGetSymbolAddress((void**)&bc, g_bc);

    cudaFuncSetAttribute(gemm_tc_kernel, cudaFuncAttributeMaxDynamicSharedMemorySize, SMEM_BYTES);

    // gemm_tc_kernel stays the 4th launch (ncu capture slot).
    prep_kernel<<<prepBlocks, TB>>>(x, dst, Wq0, Wk0, Wv0, Ws0, Wq, Wk, Wv, Ws,
                                    bq0, bk0, bv0, bs0, bq, bk, bv, bs);           // 1
    scan1_kernel<<<SCAN_BLOCKS, 256>>>();                                          // 2
    scan3_kernel<<<SCAN_BLOCKS, 256>>>();                                          // 3 (+pool zero)
    gemm_tc_kernel<<<ggrid, 256, SMEM_BYTES>>>(xh, wc, bc, N_NODES, IN_F);         // 4 (profiled)
    scatter_kernel<<<(N_EDGES + TB - 1) / TB, TB>>>(src, dst);                     // 5
    attn_kernel<<<attnBlocks, 256>>>();                                            // 6

    // layers 1..3 (HC -> HC)
    for (int l = 0; l < NLAYERS - 1; l++) {
        const __half* wl = wc + W0_SIZE + (size_t)l * WL_SIZE;
        const float*  bl = bc + (l + 1) * 1024;
        gemm_tc_kernel<<<ggrid, 256, SMEM_BYTES>>>(hh, wl, bl, N_NODES, HC);
        attn_kernel<<<attnBlocks, 256>>>();
    }

    // pooling (+ g_cnt re-zero) + fc
    pool_kernel<<<256, 256>>>(batch);
    fc_kernel<<<G_GRAPHS, OUT_F>>>(Wfc, bfc, out);
}